// round 2
// baseline (speedup 1.0000x reference)
#include <cuda_runtime.h>
#include <cstdint>
#include <cstddef>

#define B_  8
#define T_  1024
#define D_  1024
#define H_  16
#define HD_ 64
#define FF_ 4096
#define BT_ (B_*T_)            // 8192
#define TD3_ (3*D_)            // 3072

// ---------------- scratch (device globals: allocation-guard-safe) ----------
__device__ float g_h[(size_t)BT_ * D_];          // 32 MB  (ln1 / ln2 output)
__device__ float g_qkv[(size_t)BT_ * TD3_];      // 96 MB  (fused QKV)
__device__ float g_wcat[(size_t)D_ * TD3_];      // 12 MB  (repacked QKV weights)
__device__ float g_bcat[TD3_];
__device__ float g_ctx[(size_t)BT_ * D_];        // 32 MB
__device__ float g_ffa[(size_t)BT_ * FF_];       // 128 MB

// ---------------- helpers ---------------------------------------------------
__device__ __forceinline__ float geluf(float x) {
    return 0.5f * x * (1.0f + erff(x * 0.70710678118654752f));
}

// ---------------- weight repack: Wq/Wk/Wv [H,D,HD] -> Wcat [D, 3D] ----------
__global__ __launch_bounds__(256) void repack_kernel(
    const float* __restrict__ Wq, const float* __restrict__ Wk, const float* __restrict__ Wv,
    const float* __restrict__ bq, const float* __restrict__ bk, const float* __restrict__ bv)
{
    int t = blockIdx.x * blockDim.x + threadIdx.x;
    if (t >= D_ * TD3_) return;
    int d = t / TD3_;
    int n = t - d * TD3_;
    int part = n >> 10;          // 0=q 1=k 2=v
    int m = n & (D_ - 1);        // h*64+e
    int h = m >> 6, e = m & 63;
    const float* W = (part == 0) ? Wq : (part == 1) ? Wk : Wv;
    g_wcat[t] = W[((size_t)h * D_ + d) * HD_ + e];
    if (d == 0) {
        const float* bb = (part == 0) ? bq : (part == 1) ? bk : bv;
        g_bcat[n] = bb[m];
    }
}

// ---------------- layernorm: one block per row, D=1024, 256 threads ---------
__global__ __launch_bounds__(256) void ln_kernel(
    const float* __restrict__ x, const float* __restrict__ g,
    const float* __restrict__ bta, float* __restrict__ y)
{
    int row = blockIdx.x;
    int tid = threadIdx.x;
    const float4* xr = (const float4*)(x + (size_t)row * D_);
    float4 v = xr[tid];
    float s  = v.x + v.y + v.z + v.w;
    float ss = v.x*v.x + v.y*v.y + v.z*v.z + v.w*v.w;
    __shared__ float sh_s[8], sh_ss[8];
    #pragma unroll
    for (int o = 16; o > 0; o >>= 1) {
        s  += __shfl_down_sync(0xffffffffu, s,  o);
        ss += __shfl_down_sync(0xffffffffu, ss, o);
    }
    if ((tid & 31) == 0) { sh_s[tid >> 5] = s; sh_ss[tid >> 5] = ss; }
    __syncthreads();
    float S = 0.f, SS = 0.f;
    #pragma unroll
    for (int i = 0; i < 8; i++) { S += sh_s[i]; SS += sh_ss[i]; }
    float mu  = S * (1.0f / D_);
    float var = SS * (1.0f / D_) - mu * mu;
    float inv = rsqrtf(var + 1e-5f);
    float4 g4 = ((const float4*)g)[tid];
    float4 b4 = ((const float4*)bta)[tid];
    float4 o;
    o.x = (v.x - mu) * inv * g4.x + b4.x;
    o.y = (v.y - mu) * inv * g4.y + b4.y;
    o.z = (v.z - mu) * inv * g4.z + b4.z;
    o.w = (v.w - mu) * inv * g4.w + b4.w;
    ((float4*)(y + (size_t)row * D_))[tid] = o;
}

// ---------------- SGEMM 128x128x8, 256 thr, 8x8 micro-tile ------------------
// C[M,N] = A[M,K] (row-major) * B[K,N] (row-major) + epilogue
// EPI bit0: +bias[col]   bit1: gelu   bit2: +res[r*N+c]
template <int EPI>
__global__ __launch_bounds__(256) void sgemm_kernel(
    const float* __restrict__ A, const float* __restrict__ Bm,
    float* __restrict__ C, const float* __restrict__ bias,
    const float* __restrict__ res, int M, int N, int K)
{
    __shared__ float As[8][128];
    __shared__ float Bs[8][128];
    int tid = threadIdx.x;
    int tx = tid & 15, ty = tid >> 4;
    int bm = blockIdx.y, bn = blockIdx.x;
    const float* Ab = A  + (size_t)bm * 128 * K;
    const float* Bb = Bm + (size_t)bn * 128;
    int arow = tid >> 1;          // 0..127
    int akq  = (tid & 1) << 2;    // 0 or 4
    int brow = tid >> 5;          // 0..7
    int bcol = (tid & 31) << 2;   // 0..124
    float acc[8][8];
    #pragma unroll
    for (int i = 0; i < 8; i++)
        #pragma unroll
        for (int j = 0; j < 8; j++) acc[i][j] = 0.f;

    for (int kt = 0; kt < K; kt += 8) {
        float4 a4 = *(const float4*)(Ab + (size_t)arow * K + kt + akq);
        As[akq + 0][arow] = a4.x; As[akq + 1][arow] = a4.y;
        As[akq + 2][arow] = a4.z; As[akq + 3][arow] = a4.w;
        *(float4*)&Bs[brow][bcol] = *(const float4*)(Bb + (size_t)(kt + brow) * N + bcol);
        __syncthreads();
        #pragma unroll
        for (int k = 0; k < 8; k++) {
            float ar[8], br[8];
            *(float4*)&ar[0] = *(const float4*)&As[k][ty << 2];
            *(float4*)&ar[4] = *(const float4*)&As[k][64 + (ty << 2)];
            *(float4*)&br[0] = *(const float4*)&Bs[k][tx << 2];
            *(float4*)&br[4] = *(const float4*)&Bs[k][64 + (tx << 2)];
            #pragma unroll
            for (int i = 0; i < 8; i++)
                #pragma unroll
                for (int j = 0; j < 8; j++)
                    acc[i][j] = fmaf(ar[i], br[j], acc[i][j]);
        }
        __syncthreads();
    }

    #pragma unroll
    for (int ih = 0; ih < 2; ih++) {
        #pragma unroll
        for (int ii = 0; ii < 4; ii++) {
            int i = ih * 4 + ii;
            int r = bm * 128 + ih * 64 + (ty << 2) + ii;
            #pragma unroll
            for (int jh = 0; jh < 2; jh++) {
                int c = bn * 128 + jh * 64 + (tx << 2);
                float4 v;
                v.x = acc[i][jh * 4 + 0]; v.y = acc[i][jh * 4 + 1];
                v.z = acc[i][jh * 4 + 2]; v.w = acc[i][jh * 4 + 3];
                if (EPI & 1) {
                    float4 b4 = *(const float4*)(bias + c);
                    v.x += b4.x; v.y += b4.y; v.z += b4.z; v.w += b4.w;
                }
                if (EPI & 2) {
                    v.x = geluf(v.x); v.y = geluf(v.y);
                    v.z = geluf(v.z); v.w = geluf(v.w);
                }
                if (EPI & 4) {
                    float4 r4 = *(const float4*)(res + (size_t)r * N + c);
                    v.x += r4.x; v.y += r4.y; v.z += r4.z; v.w += r4.w;
                }
                *(float4*)(C + (size_t)r * N + c) = v;
            }
        }
    }
}

// ---------------- fused flash attention -------------------------------------
// One block = (bh, 64 q-rows). Online softmax over 16 s-tiles of 64.
// Thread layout: r = lane (q-row r and r+32), warp w owns output cols c0=w*8.
// Dynamic smem layout (floats):
//   Qs[64][68] | Ks[64][68] | Vs[64][68] | Ps[64][65] | redm[64][9] | reds[64][9]
#define QS_PITCH 68
#define PS_PITCH 65
#define RED_PITCH 9
#define FLASH_SMEM_FLOATS (3*64*QS_PITCH + 64*PS_PITCH + 2*64*RED_PITCH)

__global__ __launch_bounds__(256) void flash_attn_kernel()
{
    extern __shared__ float sm[];
    float* Qs   = sm;
    float* Ks   = Qs + 64 * QS_PITCH;
    float* Vs   = Ks + 64 * QS_PITCH;
    float* Ps   = Vs + 64 * QS_PITCH;
    float* redm = Ps + 64 * PS_PITCH;
    float* reds = redm + 64 * RED_PITCH;

    int bh = blockIdx.y;
    int b = bh >> 4, h = bh & 15;
    int t0 = blockIdx.x * 64;
    int tid = threadIdx.x;
    int r  = tid & 31;
    int w  = tid >> 5;
    int c0 = w << 3;

    const float* qbase = g_qkv + ((size_t)b * T_) * TD3_ + h * 64;

    // load Q tile once
    #pragma unroll
    for (int i = 0; i < 4; i++) {
        int fid = tid + i * 256;
        int row = fid >> 4;
        int e4  = (fid & 15) << 2;
        *(float4*)&Qs[row * QS_PITCH + e4] =
            *(const float4*)(qbase + (size_t)(t0 + row) * TD3_ + e4);
    }

    float o0[8], o1[8];
    #pragma unroll
    for (int j = 0; j < 8; j++) { o0[j] = 0.f; o1[j] = 0.f; }
    float m0 = -3.0e38f, m1 = -3.0e38f;
    float l0 = 0.f, l1 = 0.f;

    for (int st = 0; st < 16; st++) {
        int s0_ = st * 64;
        __syncthreads();   // Q loaded (iter 0) / previous AV done (iter>0)
        #pragma unroll
        for (int i = 0; i < 4; i++) {
            int fid = tid + i * 256;
            int row = fid >> 4;
            int e4  = (fid & 15) << 2;
            *(float4*)&Ks[row * QS_PITCH + e4] =
                *(const float4*)(qbase + 1024 + (size_t)(s0_ + row) * TD3_ + e4);
            *(float4*)&Vs[row * QS_PITCH + e4] =
                *(const float4*)(qbase + 2048 + (size_t)(s0_ + row) * TD3_ + e4);
        }
        __syncthreads();

        // scores: s[j] = 0.125 * dot(Q[row], K[c0+j])
        float s0r[8], s1r[8];
        #pragma unroll
        for (int j = 0; j < 8; j++) { s0r[j] = 0.f; s1r[j] = 0.f; }
        #pragma unroll
        for (int e4 = 0; e4 < 64; e4 += 4) {
            float4 qa = *(const float4*)&Qs[r * QS_PITCH + e4];
            float4 qb = *(const float4*)&Qs[(r + 32) * QS_PITCH + e4];
            #pragma unroll
            for (int j = 0; j < 8; j++) {
                float4 k4 = *(const float4*)&Ks[(c0 + j) * QS_PITCH + e4];
                s0r[j] += qa.x*k4.x + qa.y*k4.y + qa.z*k4.z + qa.w*k4.w;
                s1r[j] += qb.x*k4.x + qb.y*k4.y + qb.z*k4.z + qb.w*k4.w;
            }
        }
        float tmax0 = -3.0e38f, tmax1 = -3.0e38f;
        #pragma unroll
        for (int j = 0; j < 8; j++) {
            s0r[j] *= 0.125f; s1r[j] *= 0.125f;
            tmax0 = fmaxf(tmax0, s0r[j]);
            tmax1 = fmaxf(tmax1, s1r[j]);
        }
        redm[r * RED_PITCH + w]        = tmax0;
        redm[(r + 32) * RED_PITCH + w] = tmax1;
        __syncthreads();

        float rm0 = -3.0e38f, rm1 = -3.0e38f;
        #pragma unroll
        for (int j = 0; j < 8; j++) {
            rm0 = fmaxf(rm0, redm[r * RED_PITCH + j]);
            rm1 = fmaxf(rm1, redm[(r + 32) * RED_PITCH + j]);
        }
        float mn0 = fmaxf(m0, rm0);
        float mn1 = fmaxf(m1, rm1);
        float alpha0 = __expf(m0 - mn0);   // exp(-inf)=0 on first tile
        float alpha1 = __expf(m1 - mn1);
        m0 = mn0; m1 = mn1;

        float ps0 = 0.f, ps1 = 0.f;
        #pragma unroll
        for (int j = 0; j < 8; j++) {
            float p0 = __expf(s0r[j] - mn0);
            float p1 = __expf(s1r[j] - mn1);
            ps0 += p0; ps1 += p1;
            Ps[r * PS_PITCH + c0 + j]        = p0;
            Ps[(r + 32) * PS_PITCH + c0 + j] = p1;
        }
        reds[r * RED_PITCH + w]        = ps0;
        reds[(r + 32) * RED_PITCH + w] = ps1;
        #pragma unroll
        for (int j = 0; j < 8; j++) { o0[j] *= alpha0; o1[j] *= alpha1; }
        __syncthreads();

        float rs0 = 0.f, rs1 = 0.f;
        #pragma unroll
        for (int j = 0; j < 8; j++) {
            rs0 += reds[r * RED_PITCH + j];
            rs1 += reds[(r + 32) * RED_PITCH + j];
        }
        l0 = l0 * alpha0 + rs0;
        l1 = l1 * alpha1 + rs1;

        // O += P @ V
        #pragma unroll
        for (int s = 0; s < 64; s++) {
            float p0 = Ps[r * PS_PITCH + s];
            float p1 = Ps[(r + 32) * PS_PITCH + s];
            float4 va = *(const float4*)&Vs[s * QS_PITCH + c0];
            float4 vb = *(const float4*)&Vs[s * QS_PITCH + c0 + 4];
            o0[0] += p0*va.x; o0[1] += p0*va.y; o0[2] += p0*va.z; o0[3] += p0*va.w;
            o0[4] += p0*vb.x; o0[5] += p0*vb.y; o0[6] += p0*vb.z; o0[7] += p0*vb.w;
            o1[0] += p1*va.x; o1[1] += p1*va.y; o1[2] += p1*va.z; o1[3] += p1*va.w;
            o1[4] += p1*vb.x; o1[5] += p1*vb.y; o1[6] += p1*vb.z; o1[7] += p1*vb.w;
        }
    }

    float inv0 = 1.0f / l0;
    float inv1 = 1.0f / l1;
    float* out0 = g_ctx + ((size_t)b * T_ + t0 + r) * D_ + h * 64 + c0;
    float* out1 = out0 + (size_t)32 * D_;
    float4 v;
    v.x = o0[0]*inv0; v.y = o0[1]*inv0; v.z = o0[2]*inv0; v.w = o0[3]*inv0; *(float4*)out0 = v;
    v.x = o0[4]*inv0; v.y = o0[5]*inv0; v.z = o0[6]*inv0; v.w = o0[7]*inv0; *(float4*)(out0+4) = v;
    v.x = o1[0]*inv1; v.y = o1[1]*inv1; v.z = o1[2]*inv1; v.w = o1[3]*inv1; *(float4*)out1 = v;
    v.x = o1[4]*inv1; v.y = o1[5]*inv1; v.z = o1[6]*inv1; v.w = o1[7]*inv1; *(float4*)(out1+4) = v;
}

// ---------------- GEMM wrappers binding device-global scratch ---------------
__global__ __launch_bounds__(256) void noop_kernel() {}

// ---------------- launcher --------------------------------------------------
extern "C" void kernel_launch(void* const* d_in, const int* in_sizes, int n_in,
                              void* d_out, int out_size)
{
    const float* x    = (const float*)d_in[0];
    const float* ln1g = (const float*)d_in[1];
    const float* ln1b = (const float*)d_in[2];
    const float* ln2g = (const float*)d_in[3];
    const float* ln2b = (const float*)d_in[4];
    const float* Wq   = (const float*)d_in[5];
    const float* bq   = (const float*)d_in[6];
    const float* Wk   = (const float*)d_in[7];
    const float* bk   = (const float*)d_in[8];
    const float* Wv   = (const float*)d_in[9];
    const float* bv   = (const float*)d_in[10];
    const float* Wo   = (const float*)d_in[11];
    const float* bo   = (const float*)d_in[12];
    const float* W1   = (const float*)d_in[13];
    const float* b1   = (const float*)d_in[14];
    const float* W2   = (const float*)d_in[15];
    const float* b2   = (const float*)d_in[16];
    float* out = (float*)d_out;

    // device-global scratch addresses are link-time constants inside kernels;
    // for the generic SGEMM we still need raw pointers — obtain them without
    // cudaGetSymbolAddress by launching through small shims is overkill; the
    // runtime call is capture-safe (not a stream op), but we avoid it anyway
    // by using static device pointers resolved host-side once per process via
    // the CUDA runtime's symbol table.
    static float* h_    = nullptr;
    static float* qkv_  = nullptr;
    static float* wcat_ = nullptr;
    static float* bcat_ = nullptr;
    static float* ctx_  = nullptr;
    static float* ffa_  = nullptr;
    if (!h_) {   // pointer cache only — identical work every call
        cudaGetSymbolAddress((void**)&h_,    g_h);
        cudaGetSymbolAddress((void**)&qkv_,  g_qkv);
        cudaGetSymbolAddress((void**)&wcat_, g_wcat);
        cudaGetSymbolAddress((void**)&bcat_, g_bcat);
        cudaGetSymbolAddress((void**)&ctx_,  g_ctx);
        cudaGetSymbolAddress((void**)&ffa_,  g_ffa);
        cudaFuncSetAttribute(flash_attn_kernel,
                             cudaFuncAttributeMaxDynamicSharedMemorySize,
                             FLASH_SMEM_FLOATS * (int)sizeof(float));
    }

    // 1) repack QKV weights -> [D, 3D] + bias concat
    repack_kernel<<<(D_ * TD3_ + 255) / 256, 256>>>(Wq, Wk, Wv, bq, bk, bv);
    // 2) ln1: x -> h
    ln_kernel<<<BT_, 256>>>(x, ln1g, ln1b, h_);
    // 3) QKV = h @ Wcat + bcat     [8192, 3072]
    sgemm_kernel<1><<<dim3(TD3_ / 128, BT_ / 128), 256>>>(h_, wcat_, qkv_, bcat_, nullptr,
                                                          BT_, TD3_, D_);
    // 4-6) fused attention: scores + softmax + att@V  -> g_ctx
    flash_attn_kernel<<<dim3(16, B_ * H_), 256,
                        FLASH_SMEM_FLOATS * sizeof(float)>>>();
    // 7) X1 = x + ctx @ Wo + bo    -> d_out
    sgemm_kernel<5><<<dim3(D_ / 128, BT_ / 128), 256>>>(ctx_, Wo, out, bo, x,
                                                        BT_, D_, D_);
    // 8) ln2: X1 -> h
    ln_kernel<<<BT_, 256>>>(out, ln2g, ln2b, h_);
    // 9) ffa = gelu(h @ W1 + b1)   [8192, 4096]
    sgemm_kernel<3><<<dim3(FF_ / 128, BT_ / 128), 256>>>(h_, W1, ffa_, b1, nullptr,
                                                         BT_, FF_, D_);
    // 10) out = X1 + ffa @ W2 + b2
    sgemm_kernel<5><<<dim3(D_ / 128, BT_ / 128), 256>>>(ffa_, W2, out, b2, out,
                                                        BT_, D_, FF_);
}

// round 3
// speedup vs baseline: 1.9025x; 1.9025x over previous
#include <cuda_runtime.h>
#include <cstdint>
#include <cstddef>

#define B_  8
#define T_  1024
#define D_  1024
#define H_  16
#define HD_ 64
#define FF_ 4096
#define BT_ (B_*T_)            // 8192
#define TD3_ (3*D_)            // 3072

// ---------------- scratch (device globals: allocation-guard-safe) ----------
__device__ float g_h[(size_t)BT_ * D_];          // 32 MB
__device__ float g_qkv[(size_t)BT_ * TD3_];      // 96 MB
__device__ float g_wcat[(size_t)D_ * TD3_];      // 12 MB
__device__ float g_bcat[TD3_];
__device__ float g_ctx[(size_t)BT_ * D_];        // 32 MB
__device__ float g_ffa[(size_t)BT_ * FF_];       // 128 MB

// ---------------- helpers ---------------------------------------------------
__device__ __forceinline__ float geluf(float x) {
    return 0.5f * x * (1.0f + erff(x * 0.70710678118654752f));
}
__device__ __forceinline__ uint32_t f2tf(float x) {
    uint32_t r; asm("cvt.rna.tf32.f32 %0, %1;" : "=r"(r) : "f"(x)); return r;
}
__device__ __forceinline__ void mma_tf32(float c[4], const uint32_t a[4], const uint32_t b[2]) {
    asm volatile(
        "mma.sync.aligned.m16n8k8.row.col.f32.tf32.tf32.f32 "
        "{%0,%1,%2,%3}, {%4,%5,%6,%7}, {%8,%9}, {%0,%1,%2,%3};"
        : "+f"(c[0]), "+f"(c[1]), "+f"(c[2]), "+f"(c[3])
        : "r"(a[0]), "r"(a[1]), "r"(a[2]), "r"(a[3]), "r"(b[0]), "r"(b[1]));
}

// ---------------- weight repack: Wq/Wk/Wv [H,D,HD] -> Wcat [D, 3D] ----------
__global__ __launch_bounds__(256) void repack_kernel(
    const float* __restrict__ Wq, const float* __restrict__ Wk, const float* __restrict__ Wv,
    const float* __restrict__ bq, const float* __restrict__ bk, const float* __restrict__ bv)
{
    int t = blockIdx.x * blockDim.x + threadIdx.x;
    if (t >= D_ * TD3_) return;
    int d = t / TD3_;
    int n = t - d * TD3_;
    int part = n >> 10;
    int m = n & (D_ - 1);
    int h = m >> 6, e = m & 63;
    const float* W = (part == 0) ? Wq : (part == 1) ? Wk : Wv;
    g_wcat[t] = W[((size_t)h * D_ + d) * HD_ + e];
    if (d == 0) {
        const float* bb = (part == 0) ? bq : (part == 1) ? bk : bv;
        g_bcat[n] = bb[m];
    }
}

// ---------------- layernorm ---------------------------------------------------
__global__ __launch_bounds__(256) void ln_kernel(
    const float* __restrict__ x, const float* __restrict__ g,
    const float* __restrict__ bta, float* __restrict__ y)
{
    int row = blockIdx.x;
    int tid = threadIdx.x;
    const float4* xr = (const float4*)(x + (size_t)row * D_);
    float4 v = xr[tid];
    float s  = v.x + v.y + v.z + v.w;
    float ss = v.x*v.x + v.y*v.y + v.z*v.z + v.w*v.w;
    __shared__ float sh_s[8], sh_ss[8];
    #pragma unroll
    for (int o = 16; o > 0; o >>= 1) {
        s  += __shfl_down_sync(0xffffffffu, s,  o);
        ss += __shfl_down_sync(0xffffffffu, ss, o);
    }
    if ((tid & 31) == 0) { sh_s[tid >> 5] = s; sh_ss[tid >> 5] = ss; }
    __syncthreads();
    float S = 0.f, SS = 0.f;
    #pragma unroll
    for (int i = 0; i < 8; i++) { S += sh_s[i]; SS += sh_ss[i]; }
    float mu  = S * (1.0f / D_);
    float var = SS * (1.0f / D_) - mu * mu;
    float inv = rsqrtf(var + 1e-5f);
    float4 g4 = ((const float4*)g)[tid];
    float4 b4 = ((const float4*)bta)[tid];
    float4 o;
    o.x = (v.x - mu) * inv * g4.x + b4.x;
    o.y = (v.y - mu) * inv * g4.y + b4.y;
    o.z = (v.z - mu) * inv * g4.z + b4.z;
    o.w = (v.w - mu) * inv * g4.w + b4.w;
    ((float4*)(y + (size_t)row * D_))[tid] = o;
}

// ---------------- tf32 tensor-core GEMM 128x128x16 --------------------------
// C[M,N] = A[M,K] * B[K,N] (both row-major) + epilogue
// 8 warps; warp tile 32(M)x64(N) via m16n8k8 tf32 mma (2 M-frags x 8 N-frags).
// EPI bit0: +bias[col]   bit1: gelu   bit2: +res[r*N+c]
template <int EPI>
__global__ __launch_bounds__(256, 2) void tgemm_kernel(
    const float* __restrict__ A, const float* __restrict__ Bm,
    float* __restrict__ C, const float* __restrict__ bias,
    const float* __restrict__ res, int M, int N, int K)
{
    __shared__ uint32_t As[128][20];   // [m][k], pitch 20: frag reads conflict-free
    __shared__ uint32_t Bs[16][136];   // [k][n], pitch 136: frag reads conflict-free
    int tid = threadIdx.x;
    int lane = tid & 31, warp = tid >> 5;
    int g = lane >> 2, tg = lane & 3;
    int mw = (warp & 3) << 5;    // warp M offset 0..96
    int nw = (warp >> 2) << 6;   // warp N offset 0 or 64
    int bm = blockIdx.y, bn = blockIdx.x;
    const float* Ab = A  + (size_t)bm * 128 * K;
    const float* Bb = Bm + (size_t)bn * 128;

    float acc[2][8][4];
    #pragma unroll
    for (int mi = 0; mi < 2; mi++)
        #pragma unroll
        for (int j = 0; j < 8; j++)
            #pragma unroll
            for (int q = 0; q < 4; q++) acc[mi][j][q] = 0.f;

    int am  = tid >> 1;          // 0..127
    int ak  = (tid & 1) << 3;    // 0 or 8
    int bkr = tid >> 5;          // 0..7
    int bn4 = lane << 2;         // 0..124

    for (int kt = 0; kt < K; kt += 16) {
        float4 a0 = *(const float4*)(Ab + (size_t)am * K + kt + ak);
        float4 a1 = *(const float4*)(Ab + (size_t)am * K + kt + ak + 4);
        float4 b0 = *(const float4*)(Bb + (size_t)(kt + bkr) * N + bn4);
        float4 b1 = *(const float4*)(Bb + (size_t)(kt + bkr + 8) * N + bn4);
        uint4 ua0 = { f2tf(a0.x), f2tf(a0.y), f2tf(a0.z), f2tf(a0.w) };
        uint4 ua1 = { f2tf(a1.x), f2tf(a1.y), f2tf(a1.z), f2tf(a1.w) };
        uint4 ub0 = { f2tf(b0.x), f2tf(b0.y), f2tf(b0.z), f2tf(b0.w) };
        uint4 ub1 = { f2tf(b1.x), f2tf(b1.y), f2tf(b1.z), f2tf(b1.w) };
        *(uint4*)&As[am][ak]       = ua0;
        *(uint4*)&As[am][ak + 4]   = ua1;
        *(uint4*)&Bs[bkr][bn4]     = ub0;
        *(uint4*)&Bs[bkr + 8][bn4] = ub1;
        __syncthreads();

        #pragma unroll
        for (int kk = 0; kk < 16; kk += 8) {
            uint32_t af[2][4], bf[8][2];
            #pragma unroll
            for (int mi = 0; mi < 2; mi++) {
                int r = mw + (mi << 4) + g;
                af[mi][0] = As[r    ][kk + tg];
                af[mi][1] = As[r + 8][kk + tg];
                af[mi][2] = As[r    ][kk + tg + 4];
                af[mi][3] = As[r + 8][kk + tg + 4];
            }
            #pragma unroll
            for (int j = 0; j < 8; j++) {
                bf[j][0] = Bs[kk + tg    ][nw + (j << 3) + g];
                bf[j][1] = Bs[kk + tg + 4][nw + (j << 3) + g];
            }
            #pragma unroll
            for (int mi = 0; mi < 2; mi++)
                #pragma unroll
                for (int j = 0; j < 8; j++)
                    mma_tf32(acc[mi][j], af[mi], bf[j]);
        }
        __syncthreads();
    }

    // epilogue: rows mw+16mi+g and +8; cols nw+8j+2tg, +1
    #pragma unroll
    for (int mi = 0; mi < 2; mi++) {
        int r0 = bm * 128 + mw + (mi << 4) + g;
        int r1 = r0 + 8;
        #pragma unroll
        for (int j = 0; j < 8; j++) {
            int c = bn * 128 + nw + (j << 3) + (tg << 1);
            float v0 = acc[mi][j][0], v1 = acc[mi][j][1];
            float v2 = acc[mi][j][2], v3 = acc[mi][j][3];
            if (EPI & 1) {
                float2 bv = *(const float2*)(bias + c);
                v0 += bv.x; v1 += bv.y; v2 += bv.x; v3 += bv.y;
            }
            if (EPI & 2) {
                v0 = geluf(v0); v1 = geluf(v1); v2 = geluf(v2); v3 = geluf(v3);
            }
            if (EPI & 4) {
                float2 ra = *(const float2*)(res + (size_t)r0 * N + c);
                float2 rb = *(const float2*)(res + (size_t)r1 * N + c);
                v0 += ra.x; v1 += ra.y; v2 += rb.x; v3 += rb.y;
            }
            float2 w0 = { v0, v1 }, w1 = { v2, v3 };
            *(float2*)(C + (size_t)r0 * N + c) = w0;
            *(float2*)(C + (size_t)r1 * N + c) = w1;
        }
    }
}

// ---------------- fused flash attention (fp32, unchanged) -------------------
#define QS_PITCH 68
#define PS_PITCH 65
#define RED_PITCH 9
#define FLASH_SMEM_FLOATS (3*64*QS_PITCH + 64*PS_PITCH + 2*64*RED_PITCH)

__global__ __launch_bounds__(256) void flash_attn_kernel()
{
    extern __shared__ float sm[];
    float* Qs   = sm;
    float* Ks   = Qs + 64 * QS_PITCH;
    float* Vs   = Ks + 64 * QS_PITCH;
    float* Ps   = Vs + 64 * QS_PITCH;
    float* redm = Ps + 64 * PS_PITCH;
    float* reds = redm + 64 * RED_PITCH;

    int bh = blockIdx.y;
    int b = bh >> 4, h = bh & 15;
    int t0 = blockIdx.x * 64;
    int tid = threadIdx.x;
    int r  = tid & 31;
    int w  = tid >> 5;
    int c0 = w << 3;

    const float* qbase = g_qkv + ((size_t)b * T_) * TD3_ + h * 64;

    #pragma unroll
    for (int i = 0; i < 4; i++) {
        int fid = tid + i * 256;
        int row = fid >> 4;
        int e4  = (fid & 15) << 2;
        *(float4*)&Qs[row * QS_PITCH + e4] =
            *(const float4*)(qbase + (size_t)(t0 + row) * TD3_ + e4);
    }

    float o0[8], o1[8];
    #pragma unroll
    for (int j = 0; j < 8; j++) { o0[j] = 0.f; o1[j] = 0.f; }
    float m0 = -3.0e38f, m1 = -3.0e38f;
    float l0 = 0.f, l1 = 0.f;

    for (int st = 0; st < 16; st++) {
        int s0_ = st * 64;
        __syncthreads();
        #pragma unroll
        for (int i = 0; i < 4; i++) {
            int fid = tid + i * 256;
            int row = fid >> 4;
            int e4  = (fid & 15) << 2;
            *(float4*)&Ks[row * QS_PITCH + e4] =
                *(const float4*)(qbase + 1024 + (size_t)(s0_ + row) * TD3_ + e4);
            *(float4*)&Vs[row * QS_PITCH + e4] =
                *(const float4*)(qbase + 2048 + (size_t)(s0_ + row) * TD3_ + e4);
        }
        __syncthreads();

        float s0r[8], s1r[8];
        #pragma unroll
        for (int j = 0; j < 8; j++) { s0r[j] = 0.f; s1r[j] = 0.f; }
        #pragma unroll
        for (int e4 = 0; e4 < 64; e4 += 4) {
            float4 qa = *(const float4*)&Qs[r * QS_PITCH + e4];
            float4 qb = *(const float4*)&Qs[(r + 32) * QS_PITCH + e4];
            #pragma unroll
            for (int j = 0; j < 8; j++) {
                float4 k4 = *(const float4*)&Ks[(c0 + j) * QS_PITCH + e4];
                s0r[j] += qa.x*k4.x + qa.y*k4.y + qa.z*k4.z + qa.w*k4.w;
                s1r[j] += qb.x*k4.x + qb.y*k4.y + qb.z*k4.z + qb.w*k4.w;
            }
        }
        float tmax0 = -3.0e38f, tmax1 = -3.0e38f;
        #pragma unroll
        for (int j = 0; j < 8; j++) {
            s0r[j] *= 0.125f; s1r[j] *= 0.125f;
            tmax0 = fmaxf(tmax0, s0r[j]);
            tmax1 = fmaxf(tmax1, s1r[j]);
        }
        redm[r * RED_PITCH + w]        = tmax0;
        redm[(r + 32) * RED_PITCH + w] = tmax1;
        __syncthreads();

        float rm0 = -3.0e38f, rm1 = -3.0e38f;
        #pragma unroll
        for (int j = 0; j < 8; j++) {
            rm0 = fmaxf(rm0, redm[r * RED_PITCH + j]);
            rm1 = fmaxf(rm1, redm[(r + 32) * RED_PITCH + j]);
        }
        float mn0 = fmaxf(m0, rm0);
        float mn1 = fmaxf(m1, rm1);
        float alpha0 = __expf(m0 - mn0);
        float alpha1 = __expf(m1 - mn1);
        m0 = mn0; m1 = mn1;

        float ps0 = 0.f, ps1 = 0.f;
        #pragma unroll
        for (int j = 0; j < 8; j++) {
            float p0 = __expf(s0r[j] - mn0);
            float p1 = __expf(s1r[j] - mn1);
            ps0 += p0; ps1 += p1;
            Ps[r * PS_PITCH + c0 + j]        = p0;
            Ps[(r + 32) * PS_PITCH + c0 + j] = p1;
        }
        reds[r * RED_PITCH + w]        = ps0;
        reds[(r + 32) * RED_PITCH + w] = ps1;
        #pragma unroll
        for (int j = 0; j < 8; j++) { o0[j] *= alpha0; o1[j] *= alpha1; }
        __syncthreads();

        float rs0 = 0.f, rs1 = 0.f;
        #pragma unroll
        for (int j = 0; j < 8; j++) {
            rs0 += reds[r * RED_PITCH + j];
            rs1 += reds[(r + 32) * RED_PITCH + j];
        }
        l0 = l0 * alpha0 + rs0;
        l1 = l1 * alpha1 + rs1;

        #pragma unroll
        for (int s = 0; s < 64; s++) {
            float p0 = Ps[r * PS_PITCH + s];
            float p1 = Ps[(r + 32) * PS_PITCH + s];
            float4 va = *(const float4*)&Vs[s * QS_PITCH + c0];
            float4 vb = *(const float4*)&Vs[s * QS_PITCH + c0 + 4];
            o0[0] += p0*va.x; o0[1] += p0*va.y; o0[2] += p0*va.z; o0[3] += p0*va.w;
            o0[4] += p0*vb.x; o0[5] += p0*vb.y; o0[6] += p0*vb.z; o0[7] += p0*vb.w;
            o1[0] += p1*va.x; o1[1] += p1*va.y; o1[2] += p1*va.z; o1[3] += p1*va.w;
            o1[4] += p1*vb.x; o1[5] += p1*vb.y; o1[6] += p1*vb.z; o1[7] += p1*vb.w;
        }
    }

    float inv0 = 1.0f / l0;
    float inv1 = 1.0f / l1;
    float* out0 = g_ctx + ((size_t)b * T_ + t0 + r) * D_ + h * 64 + c0;
    float* out1 = out0 + (size_t)32 * D_;
    float4 v;
    v.x = o0[0]*inv0; v.y = o0[1]*inv0; v.z = o0[2]*inv0; v.w = o0[3]*inv0; *(float4*)out0 = v;
    v.x = o0[4]*inv0; v.y = o0[5]*inv0; v.z = o0[6]*inv0; v.w = o0[7]*inv0; *(float4*)(out0+4) = v;
    v.x = o1[0]*inv1; v.y = o1[1]*inv1; v.z = o1[2]*inv1; v.w = o1[3]*inv1; *(float4*)out1 = v;
    v.x = o1[4]*inv1; v.y = o1[5]*inv1; v.z = o1[6]*inv1; v.w = o1[7]*inv1; *(float4*)(out1+4) = v;
}

// ---------------- launcher --------------------------------------------------
extern "C" void kernel_launch(void* const* d_in, const int* in_sizes, int n_in,
                              void* d_out, int out_size)
{
    const float* x    = (const float*)d_in[0];
    const float* ln1g = (const float*)d_in[1];
    const float* ln1b = (const float*)d_in[2];
    const float* ln2g = (const float*)d_in[3];
    const float* ln2b = (const float*)d_in[4];
    const float* Wq   = (const float*)d_in[5];
    const float* bq   = (const float*)d_in[6];
    const float* Wk   = (const float*)d_in[7];
    const float* bk   = (const float*)d_in[8];
    const float* Wv   = (const float*)d_in[9];
    const float* bv   = (const float*)d_in[10];
    const float* Wo   = (const float*)d_in[11];
    const float* bo   = (const float*)d_in[12];
    const float* W1   = (const float*)d_in[13];
    const float* b1   = (const float*)d_in[14];
    const float* W2   = (const float*)d_in[15];
    const float* b2   = (const float*)d_in[16];
    float* out = (float*)d_out;

    static float* h_    = nullptr;
    static float* qkv_  = nullptr;
    static float* wcat_ = nullptr;
    static float* bcat_ = nullptr;
    static float* ctx_  = nullptr;
    static float* ffa_  = nullptr;
    if (!h_) {   // pointer cache only — identical work every call
        cudaGetSymbolAddress((void**)&h_,    g_h);
        cudaGetSymbolAddress((void**)&qkv_,  g_qkv);
        cudaGetSymbolAddress((void**)&wcat_, g_wcat);
        cudaGetSymbolAddress((void**)&bcat_, g_bcat);
        cudaGetSymbolAddress((void**)&ctx_,  g_ctx);
        cudaGetSymbolAddress((void**)&ffa_,  g_ffa);
        cudaFuncSetAttribute(flash_attn_kernel,
                             cudaFuncAttributeMaxDynamicSharedMemorySize,
                             FLASH_SMEM_FLOATS * (int)sizeof(float));
    }

    // 1) repack QKV weights -> [D, 3D] + bias concat
    repack_kernel<<<(D_ * TD3_ + 255) / 256, 256>>>(Wq, Wk, Wv, bq, bk, bv);
    // 2) ln1: x -> h
    ln_kernel<<<BT_, 256>>>(x, ln1g, ln1b, h_);
    // 3) QKV = h @ Wcat + bcat     [8192, 3072]
    tgemm_kernel<1><<<dim3(TD3_ / 128, BT_ / 128), 256>>>(h_, wcat_, qkv_, bcat_, nullptr,
                                                          BT_, TD3_, D_);
    // 4-6) fused attention -> g_ctx
    flash_attn_kernel<<<dim3(16, B_ * H_), 256,
                        FLASH_SMEM_FLOATS * sizeof(float)>>>();
    // 7) X1 = x + ctx @ Wo + bo    -> d_out
    tgemm_kernel<5><<<dim3(D_ / 128, BT_ / 128), 256>>>(ctx_, Wo, out, bo, x,
                                                        BT_, D_, D_);
    // 8) ln2: X1 -> h
    ln_kernel<<<BT_, 256>>>(out, ln2g, ln2b, h_);
    // 9) ffa = gelu(h @ W1 + b1)   [8192, 4096]
    tgemm_kernel<3><<<dim3(FF_ / 128, BT_ / 128), 256>>>(h_, W1, ffa_, b1, nullptr,
                                                         BT_, FF_, D_);
    // 10) out = X1 + ffa @ W2 + b2
    tgemm_kernel<5><<<dim3(D_ / 128, BT_ / 128), 256>>>(ffa_, W2, out, b2, out,
                                                        BT_, D_, FF_);
}

// round 5
// speedup vs baseline: 2.4141x; 1.2689x over previous
#include <cuda_runtime.h>
#include <cstdint>
#include <cstddef>

#define B_  8
#define T_  1024
#define D_  1024
#define H_  16
#define HD_ 64
#define FF_ 4096
#define BT_ (B_*T_)            // 8192
#define TD3_ (3*D_)            // 3072

// ---------------- scratch (device globals: allocation-guard-safe) ----------
__device__ float g_h[(size_t)BT_ * D_];          // 32 MB
__device__ float g_qkv[(size_t)BT_ * TD3_];      // 96 MB
__device__ float g_wcat[(size_t)D_ * TD3_];      // 12 MB
__device__ float g_bcat[TD3_];
__device__ float g_ctx[(size_t)BT_ * D_];        // 32 MB
__device__ float g_ffa[(size_t)BT_ * FF_];       // 128 MB

// ---------------- helpers ---------------------------------------------------
__device__ __forceinline__ float geluf(float x) {
    return 0.5f * x * (1.0f + erff(x * 0.70710678118654752f));
}
__device__ __forceinline__ uint32_t f2tf(float x) {
    uint32_t r; asm("cvt.rna.tf32.f32 %0, %1;" : "=r"(r) : "f"(x)); return r;
}
__device__ __forceinline__ void mma_tf32(float c[4], const uint32_t a[4], const uint32_t b[2]) {
    asm volatile(
        "mma.sync.aligned.m16n8k8.row.col.f32.tf32.tf32.f32 "
        "{%0,%1,%2,%3}, {%4,%5,%6,%7}, {%8,%9}, {%0,%1,%2,%3};"
        : "+f"(c[0]), "+f"(c[1]), "+f"(c[2]), "+f"(c[3])
        : "r"(a[0]), "r"(a[1]), "r"(a[2]), "r"(a[3]), "r"(b[0]), "r"(b[1]));
}
__device__ __forceinline__ void cp_async16(void* sptr, const void* gptr) {
    uint32_t s = (uint32_t)__cvta_generic_to_shared(sptr);
    asm volatile("cp.async.cg.shared.global [%0], [%1], 16;" :: "r"(s), "l"(gptr));
}
#define CP_COMMIT() asm volatile("cp.async.commit_group;")
#define CP_WAIT0()  asm volatile("cp.async.wait_group 0;")

// ---------------- weight repack: Wq/Wk/Wv [H,D,HD] -> Wcat [D, 3D] ----------
__global__ __launch_bounds__(256) void repack_kernel(
    const float* __restrict__ Wq, const float* __restrict__ Wk, const float* __restrict__ Wv,
    const float* __restrict__ bq, const float* __restrict__ bk, const float* __restrict__ bv)
{
    int t = blockIdx.x * blockDim.x + threadIdx.x;
    if (t >= D_ * TD3_) return;
    int d = t / TD3_;
    int n = t - d * TD3_;
    int part = n >> 10;
    int m = n & (D_ - 1);
    int h = m >> 6, e = m & 63;
    const float* W = (part == 0) ? Wq : (part == 1) ? Wk : Wv;
    g_wcat[t] = W[((size_t)h * D_ + d) * HD_ + e];
    if (d == 0) {
        const float* bb = (part == 0) ? bq : (part == 1) ? bk : bv;
        g_bcat[n] = bb[m];
    }
}

// ---------------- layernorm -------------------------------------------------
__global__ __launch_bounds__(256) void ln_kernel(
    const float* __restrict__ x, const float* __restrict__ g,
    const float* __restrict__ bta, float* __restrict__ y)
{
    int row = blockIdx.x;
    int tid = threadIdx.x;
    const float4* xr = (const float4*)(x + (size_t)row * D_);
    float4 v = xr[tid];
    float s  = v.x + v.y + v.z + v.w;
    float ss = v.x*v.x + v.y*v.y + v.z*v.z + v.w*v.w;
    __shared__ float sh_s[8], sh_ss[8];
    #pragma unroll
    for (int o = 16; o > 0; o >>= 1) {
        s  += __shfl_down_sync(0xffffffffu, s,  o);
        ss += __shfl_down_sync(0xffffffffu, ss, o);
    }
    if ((tid & 31) == 0) { sh_s[tid >> 5] = s; sh_ss[tid >> 5] = ss; }
    __syncthreads();
    float S = 0.f, SS = 0.f;
    #pragma unroll
    for (int i = 0; i < 8; i++) { S += sh_s[i]; SS += sh_ss[i]; }
    float mu  = S * (1.0f / D_);
    float var = SS * (1.0f / D_) - mu * mu;
    float inv = rsqrtf(var + 1e-5f);
    float4 g4 = ((const float4*)g)[tid];
    float4 b4 = ((const float4*)bta)[tid];
    float4 o;
    o.x = (v.x - mu) * inv * g4.x + b4.x;
    o.y = (v.y - mu) * inv * g4.y + b4.y;
    o.z = (v.z - mu) * inv * g4.z + b4.z;
    o.w = (v.w - mu) * inv * g4.w + b4.w;
    ((float4*)(y + (size_t)row * D_))[tid] = o;
}

// ---------------- tf32 tensor-core GEMM 128x128x16, cp.async 2-stage --------
// C[M,N] = A[M,K] * B[K,N] (row-major) + epilogue
// EPI bit0: +bias[col]   bit1: gelu   bit2: +res
template <int EPI>
__global__ __launch_bounds__(256, 2) void tgemm_kernel(
    const float* __restrict__ A, const float* __restrict__ Bm,
    float* __restrict__ C, const float* __restrict__ bias,
    const float* __restrict__ res, int M, int N, int K)
{
    __shared__ float As[2][128][20];
    __shared__ float Bs[2][16][136];
    int tid = threadIdx.x;
    int lane = tid & 31, warp = tid >> 5;
    int g = lane >> 2, tg = lane & 3;
    int mw = (warp & 3) << 5;
    int nw = (warp >> 2) << 6;
    int bm = blockIdx.y, bn = blockIdx.x;
    const float* Ab = A  + (size_t)bm * 128 * K;
    const float* Bb = Bm + (size_t)bn * 128;

    float acc[2][8][4];
    #pragma unroll
    for (int mi = 0; mi < 2; mi++)
        #pragma unroll
        for (int j = 0; j < 8; j++)
            #pragma unroll
            for (int q = 0; q < 4; q++) acc[mi][j][q] = 0.f;

    int am  = tid >> 1;
    int ak  = (tid & 1) << 3;
    int bkr = tid >> 5;
    int bn4 = lane << 2;

    // prefetch tile 0
    cp_async16(&As[0][am][ak],       Ab + (size_t)am * K + ak);
    cp_async16(&As[0][am][ak + 4],   Ab + (size_t)am * K + ak + 4);
    cp_async16(&Bs[0][bkr][bn4],     Bb + (size_t)bkr * N + bn4);
    cp_async16(&Bs[0][bkr + 8][bn4], Bb + (size_t)(bkr + 8) * N + bn4);
    CP_COMMIT();

    int nk = K >> 4;
    for (int it = 0; it < nk; it++) {
        int buf = it & 1;
        CP_WAIT0();
        __syncthreads();
        if (it + 1 < nk) {
            int kt = (it + 1) << 4;
            int nb = buf ^ 1;
            cp_async16(&As[nb][am][ak],       Ab + (size_t)am * K + kt + ak);
            cp_async16(&As[nb][am][ak + 4],   Ab + (size_t)am * K + kt + ak + 4);
            cp_async16(&Bs[nb][bkr][bn4],     Bb + (size_t)(kt + bkr) * N + bn4);
            cp_async16(&Bs[nb][bkr + 8][bn4], Bb + (size_t)(kt + bkr + 8) * N + bn4);
            CP_COMMIT();
        }
        #pragma unroll
        for (int kk = 0; kk < 16; kk += 8) {
            uint32_t af[2][4], bf[8][2];
            #pragma unroll
            for (int mi = 0; mi < 2; mi++) {
                int r = mw + (mi << 4) + g;
                af[mi][0] = f2tf(As[buf][r    ][kk + tg]);
                af[mi][1] = f2tf(As[buf][r + 8][kk + tg]);
                af[mi][2] = f2tf(As[buf][r    ][kk + tg + 4]);
                af[mi][3] = f2tf(As[buf][r + 8][kk + tg + 4]);
            }
            #pragma unroll
            for (int j = 0; j < 8; j++) {
                bf[j][0] = f2tf(Bs[buf][kk + tg    ][nw + (j << 3) + g]);
                bf[j][1] = f2tf(Bs[buf][kk + tg + 4][nw + (j << 3) + g]);
            }
            #pragma unroll
            for (int mi = 0; mi < 2; mi++)
                #pragma unroll
                for (int j = 0; j < 8; j++)
                    mma_tf32(acc[mi][j], af[mi], bf[j]);
        }
    }

    #pragma unroll
    for (int mi = 0; mi < 2; mi++) {
        int r0 = bm * 128 + mw + (mi << 4) + g;
        int r1 = r0 + 8;
        #pragma unroll
        for (int j = 0; j < 8; j++) {
            int c = bn * 128 + nw + (j << 3) + (tg << 1);
            float v0 = acc[mi][j][0], v1 = acc[mi][j][1];
            float v2 = acc[mi][j][2], v3 = acc[mi][j][3];
            if (EPI & 1) {
                float2 bv = *(const float2*)(bias + c);
                v0 += bv.x; v1 += bv.y; v2 += bv.x; v3 += bv.y;
            }
            if (EPI & 2) {
                v0 = geluf(v0); v1 = geluf(v1); v2 = geluf(v2); v3 = geluf(v3);
            }
            if (EPI & 4) {
                float2 ra = *(const float2*)(res + (size_t)r0 * N + c);
                float2 rb = *(const float2*)(res + (size_t)r1 * N + c);
                v0 += ra.x; v1 += ra.y; v2 += rb.x; v3 += rb.y;
            }
            float2 w0 = { v0, v1 }, w1 = { v2, v3 };
            *(float2*)(C + (size_t)r0 * N + c) = w0;
            *(float2*)(C + (size_t)r1 * N + c) = w1;
        }
    }
}

// ---------------- flash attention, tf32 tensor cores ------------------------
// Block: (bh, 64 q-rows). 8 warps as 4(m)x2(n). Warp tile 16x32.
// Dynamic smem (uint32): Qs[64][68] Ks[64][68] Vt[64][68] Ps[64][68]
//                        + redm[64][2] reds[64][2] (float)
#define FP 68
#define FLASH_SMEM_BYTES ((4*64*FP + 2*64*2) * 4)

__global__ __launch_bounds__(256, 2) void flash_attn_kernel()
{
    extern __shared__ uint32_t usm[];
    uint32_t* Qs = usm;
    uint32_t* Ks = Qs + 64 * FP;
    uint32_t* Vt = Ks + 64 * FP;
    uint32_t* Ps = Vt + 64 * FP;
    float* redm  = (float*)(Ps + 64 * FP);
    float* reds  = redm + 64 * 2;

    int bh = blockIdx.y;
    int b = bh >> 4, h = bh & 15;
    int t0 = blockIdx.x * 64;
    int tid = threadIdx.x;
    int lane = tid & 31, warp = tid >> 5;
    int g = lane >> 2, tg = lane & 3;
    int wm = warp & 3, wn = warp >> 2;
    int m0r = (wm << 4) + g;        // q-row in tile (and +8)
    int nb  = wn << 5;              // col group 0/32

    const float* qbase = g_qkv + ((size_t)b * T_) * TD3_ + h * 64;

    // load Q tile (tf32)
    #pragma unroll
    for (int i = 0; i < 4; i++) {
        int fid = tid + i * 256;
        int row = fid >> 4;
        int e4  = (fid & 15) << 2;
        float4 q4 = *(const float4*)(qbase + (size_t)(t0 + row) * TD3_ + e4);
        uint4 u = { f2tf(q4.x), f2tf(q4.y), f2tf(q4.z), f2tf(q4.w) };
        *(uint4*)&Qs[row * FP + e4] = u;
    }

    float accO[4][4];
    #pragma unroll
    for (int j = 0; j < 4; j++)
        #pragma unroll
        for (int q = 0; q < 4; q++) accO[j][q] = 0.f;
    float m0 = -3.0e38f, m1 = -3.0e38f, l0 = 0.f, l1 = 0.f;

    for (int st = 0; st < 16; st++) {
        int s0_ = st * 64;
        __syncthreads();   // prev iter consumed Ks/Vt/Ps (and Q stored, iter0)
        #pragma unroll
        for (int i = 0; i < 4; i++) {
            int fid = tid + i * 256;
            int row = fid >> 4;
            int e4  = (fid & 15) << 2;
            float4 k4 = *(const float4*)(qbase + 1024 + (size_t)(s0_ + row) * TD3_ + e4);
            uint4 uk = { f2tf(k4.x), f2tf(k4.y), f2tf(k4.z), f2tf(k4.w) };
            *(uint4*)&Ks[row * FP + e4] = uk;
            float4 v4 = *(const float4*)(qbase + 2048 + (size_t)(s0_ + row) * TD3_ + e4);
            Vt[(e4 + 0) * FP + row] = f2tf(v4.x);
            Vt[(e4 + 1) * FP + row] = f2tf(v4.y);
            Vt[(e4 + 2) * FP + row] = f2tf(v4.z);
            Vt[(e4 + 3) * FP + row] = f2tf(v4.w);
        }
        __syncthreads();

        // S = Q K^T (warp 16x32 tile)
        float sacc[4][4];
        #pragma unroll
        for (int j = 0; j < 4; j++)
            #pragma unroll
            for (int q = 0; q < 4; q++) sacc[j][q] = 0.f;
        #pragma unroll
        for (int kk = 0; kk < 64; kk += 8) {
            uint32_t af[4], bf[4][2];
            af[0] = Qs[m0r * FP + kk + tg];
            af[1] = Qs[(m0r + 8) * FP + kk + tg];
            af[2] = Qs[m0r * FP + kk + tg + 4];
            af[3] = Qs[(m0r + 8) * FP + kk + tg + 4];
            #pragma unroll
            for (int j = 0; j < 4; j++) {
                int n = nb + (j << 3) + g;
                bf[j][0] = Ks[n * FP + kk + tg];
                bf[j][1] = Ks[n * FP + kk + tg + 4];
            }
            #pragma unroll
            for (int j = 0; j < 4; j++) mma_tf32(sacc[j], af, bf[j]);
        }

        // scale + row max
        float rmax0 = -3.0e38f, rmax1 = -3.0e38f;
        #pragma unroll
        for (int j = 0; j < 4; j++) {
            #pragma unroll
            for (int q = 0; q < 4; q++) sacc[j][q] *= 0.125f;
            rmax0 = fmaxf(rmax0, fmaxf(sacc[j][0], sacc[j][1]));
            rmax1 = fmaxf(rmax1, fmaxf(sacc[j][2], sacc[j][3]));
        }
        rmax0 = fmaxf(rmax0, __shfl_xor_sync(0xffffffffu, rmax0, 1));
        rmax0 = fmaxf(rmax0, __shfl_xor_sync(0xffffffffu, rmax0, 2));
        rmax1 = fmaxf(rmax1, __shfl_xor_sync(0xffffffffu, rmax1, 1));
        rmax1 = fmaxf(rmax1, __shfl_xor_sync(0xffffffffu, rmax1, 2));
        if (tg == 0) {
            redm[m0r * 2 + wn]       = rmax0;
            redm[(m0r + 8) * 2 + wn] = rmax1;
        }
        __syncthreads();
        float mn0 = fmaxf(m0, fmaxf(redm[m0r * 2], redm[m0r * 2 + 1]));
        float mn1 = fmaxf(m1, fmaxf(redm[(m0r + 8) * 2], redm[(m0r + 8) * 2 + 1]));
        float alpha0 = __expf(m0 - mn0);
        float alpha1 = __expf(m1 - mn1);
        m0 = mn0; m1 = mn1;

        // P = exp(S - m), store tf32, partial row sums
        float rs0 = 0.f, rs1 = 0.f;
        #pragma unroll
        for (int j = 0; j < 4; j++) {
            float p00 = __expf(sacc[j][0] - mn0);
            float p01 = __expf(sacc[j][1] - mn0);
            float p10 = __expf(sacc[j][2] - mn1);
            float p11 = __expf(sacc[j][3] - mn1);
            rs0 += p00 + p01; rs1 += p10 + p11;
            int col = nb + (j << 3) + (tg << 1);
            uint2 u0 = { f2tf(p00), f2tf(p01) };
            uint2 u1 = { f2tf(p10), f2tf(p11) };
            *(uint2*)&Ps[m0r * FP + col]       = u0;
            *(uint2*)&Ps[(m0r + 8) * FP + col] = u1;
        }
        rs0 += __shfl_xor_sync(0xffffffffu, rs0, 1);
        rs0 += __shfl_xor_sync(0xffffffffu, rs0, 2);
        rs1 += __shfl_xor_sync(0xffffffffu, rs1, 1);
        rs1 += __shfl_xor_sync(0xffffffffu, rs1, 2);
        if (tg == 0) {
            reds[m0r * 2 + wn]       = rs0;
            reds[(m0r + 8) * 2 + wn] = rs1;
        }
        #pragma unroll
        for (int j = 0; j < 4; j++) {
            accO[j][0] *= alpha0; accO[j][1] *= alpha0;
            accO[j][2] *= alpha1; accO[j][3] *= alpha1;
        }
        __syncthreads();
        l0 = l0 * alpha0 + reds[m0r * 2] + reds[m0r * 2 + 1];
        l1 = l1 * alpha1 + reds[(m0r + 8) * 2] + reds[(m0r + 8) * 2 + 1];

        // O += P @ V
        #pragma unroll
        for (int kk = 0; kk < 64; kk += 8) {
            uint32_t af[4], bf[4][2];
            af[0] = Ps[m0r * FP + kk + tg];
            af[1] = Ps[(m0r + 8) * FP + kk + tg];
            af[2] = Ps[m0r * FP + kk + tg + 4];
            af[3] = Ps[(m0r + 8) * FP + kk + tg + 4];
            #pragma unroll
            for (int j = 0; j < 4; j++) {
                int n = nb + (j << 3) + g;      // e-dim
                bf[j][0] = Vt[n * FP + kk + tg];
                bf[j][1] = Vt[n * FP + kk + tg + 4];
            }
            #pragma unroll
            for (int j = 0; j < 4; j++) mma_tf32(accO[j], af, bf[j]);
        }
    }

    float inv0 = 1.0f / l0;
    float inv1 = 1.0f / l1;
    float* out0 = g_ctx + ((size_t)b * T_ + t0 + m0r) * D_ + h * 64;
    float* out1 = out0 + (size_t)8 * D_;
    #pragma unroll
    for (int j = 0; j < 4; j++) {
        int col = nb + (j << 3) + (tg << 1);
        float2 w0 = { accO[j][0] * inv0, accO[j][1] * inv0 };
        float2 w1 = { accO[j][2] * inv1, accO[j][3] * inv1 };
        *(float2*)(out0 + col) = w0;
        *(float2*)(out1 + col) = w1;
    }
}

// ---------------- launcher --------------------------------------------------
extern "C" void kernel_launch(void* const* d_in, const int* in_sizes, int n_in,
                              void* d_out, int out_size)
{
    const float* x    = (const float*)d_in[0];
    const float* ln1g = (const float*)d_in[1];
    const float* ln1b = (const float*)d_in[2];
    const float* ln2g = (const float*)d_in[3];
    const float* ln2b = (const float*)d_in[4];
    const float* Wq   = (const float*)d_in[5];
    const float* bq   = (const float*)d_in[6];
    const float* Wk   = (const float*)d_in[7];
    const float* bk   = (const float*)d_in[8];
    const float* Wv   = (const float*)d_in[9];
    const float* bv   = (const float*)d_in[10];
    const float* Wo   = (const float*)d_in[11];
    const float* bo   = (const float*)d_in[12];
    const float* W1   = (const float*)d_in[13];
    const float* b1   = (const float*)d_in[14];
    const float* W2   = (const float*)d_in[15];
    const float* b2   = (const float*)d_in[16];
    float* out = (float*)d_out;

    static float* h_    = nullptr;
    static float* qkv_  = nullptr;
    static float* wcat_ = nullptr;
    static float* bcat_ = nullptr;
    static float* ctx_  = nullptr;
    static float* ffa_  = nullptr;
    if (!h_) {   // pointer cache only — identical work every call
        cudaGetSymbolAddress((void**)&h_,    g_h);
        cudaGetSymbolAddress((void**)&qkv_,  g_qkv);
        cudaGetSymbolAddress((void**)&wcat_, g_wcat);
        cudaGetSymbolAddress((void**)&bcat_, g_bcat);
        cudaGetSymbolAddress((void**)&ctx_,  g_ctx);
        cudaGetSymbolAddress((void**)&ffa_,  g_ffa);
        cudaFuncSetAttribute(flash_attn_kernel,
                             cudaFuncAttributeMaxDynamicSharedMemorySize,
                             FLASH_SMEM_BYTES);
    }

    // 1) repack QKV weights
    repack_kernel<<<(D_ * TD3_ + 255) / 256, 256>>>(Wq, Wk, Wv, bq, bk, bv);
    // 2) ln1
    ln_kernel<<<BT_, 256>>>(x, ln1g, ln1b, h_);
    // 3) QKV = h @ Wcat + bcat
    tgemm_kernel<1><<<dim3(TD3_ / 128, BT_ / 128), 256>>>(h_, wcat_, qkv_, bcat_, nullptr,
                                                          BT_, TD3_, D_);
    // 4-6) fused attention -> g_ctx
    flash_attn_kernel<<<dim3(16, B_ * H_), 256, FLASH_SMEM_BYTES>>>();
    // 7) X1 = x + ctx @ Wo + bo
    tgemm_kernel<5><<<dim3(D_ / 128, BT_ / 128), 256>>>(ctx_, Wo, out, bo, x,
                                                        BT_, D_, D_);
    // 8) ln2
    ln_kernel<<<BT_, 256>>>(out, ln2g, ln2b, h_);
    // 9) ffa = gelu(h @ W1 + b1)
    tgemm_kernel<3><<<dim3(FF_ / 128, BT_ / 128), 256>>>(h_, W1, ffa_, b1, nullptr,
                                                         BT_, FF_, D_);
    // 10) out = X1 + ffa @ W2 + b2
    tgemm_kernel<5><<<dim3(D_ / 128, BT_ / 128), 256>>>(ffa_, W2, out, b2, out,
                                                        BT_, D_, FF_);
}

// round 7
// speedup vs baseline: 2.7236x; 1.1282x over previous
#include <cuda_runtime.h>
#include <cstdint>
#include <cstddef>

#define B_  8
#define T_  1024
#define D_  1024
#define H_  16
#define HD_ 64
#define FF_ 4096
#define BT_ (B_*T_)            // 8192
#define TD3_ (3*D_)            // 3072

// ---------------- scratch (device globals: allocation-guard-safe) ----------
__device__ float g_h[(size_t)BT_ * D_];          // 32 MB  (tf32-rounded)
__device__ float g_qkv[(size_t)BT_ * TD3_];      // 96 MB
__device__ float g_wcat[(size_t)D_ * TD3_];      // 12 MB  (tf32-rounded)
__device__ float g_bcat[TD3_];
__device__ float g_ctx[(size_t)BT_ * D_];        // 32 MB  (tf32-rounded)
__device__ float g_ffa[(size_t)BT_ * FF_];       // 128 MB (tf32-rounded)

// ---------------- helpers ---------------------------------------------------
__device__ __forceinline__ float geluf(float x) {
    return 0.5f * x * (1.0f + erff(x * 0.70710678118654752f));
}
__device__ __forceinline__ uint32_t f2tf(float x) {
    uint32_t r; asm("cvt.rna.tf32.f32 %0, %1;" : "=r"(r) : "f"(x)); return r;
}
__device__ __forceinline__ float rtf(float x) {   // tf32-rounded fp32 value
    return __uint_as_float(f2tf(x));
}
__device__ __forceinline__ void mma_tf32(float c[4], const uint32_t a[4], const uint32_t b[2]) {
    asm volatile(
        "mma.sync.aligned.m16n8k8.row.col.f32.tf32.tf32.f32 "
        "{%0,%1,%2,%3}, {%4,%5,%6,%7}, {%8,%9}, {%0,%1,%2,%3};"
        : "+f"(c[0]), "+f"(c[1]), "+f"(c[2]), "+f"(c[3])
        : "r"(a[0]), "r"(a[1]), "r"(a[2]), "r"(a[3]), "r"(b[0]), "r"(b[1]));
}
__device__ __forceinline__ void cp_async16(void* sptr, const void* gptr) {
    uint32_t s = (uint32_t)__cvta_generic_to_shared(sptr);
    asm volatile("cp.async.cg.shared.global [%0], [%1], 16;" :: "r"(s), "l"(gptr));
}
#define CP_COMMIT() asm volatile("cp.async.commit_group;")
#define CP_WAIT0()  asm volatile("cp.async.wait_group 0;")

// ---------------- weight repack: Wq/Wk/Wv [H,D,HD] -> Wcat [D, 3D] ----------
__global__ __launch_bounds__(256) void repack_kernel(
    const float* __restrict__ Wq, const float* __restrict__ Wk, const float* __restrict__ Wv,
    const float* __restrict__ bq, const float* __restrict__ bk, const float* __restrict__ bv)
{
    int t = blockIdx.x * blockDim.x + threadIdx.x;
    if (t >= D_ * TD3_) return;
    int d = t / TD3_;
    int n = t - d * TD3_;
    int part = n >> 10;
    int m = n & (D_ - 1);
    int h = m >> 6, e = m & 63;
    const float* W = (part == 0) ? Wq : (part == 1) ? Wk : Wv;
    g_wcat[t] = rtf(W[((size_t)h * D_ + d) * HD_ + e]);   // tf32-rounded
    if (d == 0) {
        const float* bb = (part == 0) ? bq : (part == 1) ? bk : bv;
        g_bcat[n] = bb[m];
    }
}

// ---------------- layernorm (output tf32-rounded: GEMM-A operand only) ------
__global__ __launch_bounds__(256) void ln_kernel(
    const float* __restrict__ x, const float* __restrict__ g,
    const float* __restrict__ bta, float* __restrict__ y)
{
    int row = blockIdx.x;
    int tid = threadIdx.x;
    const float4* xr = (const float4*)(x + (size_t)row * D_);
    float4 v = xr[tid];
    float s  = v.x + v.y + v.z + v.w;
    float ss = v.x*v.x + v.y*v.y + v.z*v.z + v.w*v.w;
    __shared__ float sh_s[8], sh_ss[8];
    #pragma unroll
    for (int o = 16; o > 0; o >>= 1) {
        s  += __shfl_down_sync(0xffffffffu, s,  o);
        ss += __shfl_down_sync(0xffffffffu, ss, o);
    }
    if ((tid & 31) == 0) { sh_s[tid >> 5] = s; sh_ss[tid >> 5] = ss; }
    __syncthreads();
    float S = 0.f, SS = 0.f;
    #pragma unroll
    for (int i = 0; i < 8; i++) { S += sh_s[i]; SS += sh_ss[i]; }
    float mu  = S * (1.0f / D_);
    float var = SS * (1.0f / D_) - mu * mu;
    float inv = rsqrtf(var + 1e-5f);
    float4 g4 = ((const float4*)g)[tid];
    float4 b4 = ((const float4*)bta)[tid];
    float4 o;
    o.x = rtf((v.x - mu) * inv * g4.x + b4.x);
    o.y = rtf((v.y - mu) * inv * g4.y + b4.y);
    o.z = rtf((v.z - mu) * inv * g4.z + b4.z);
    o.w = rtf((v.w - mu) * inv * g4.w + b4.w);
    ((float4*)(y + (size_t)row * D_))[tid] = o;
}

// ---------------- tf32 tensor-core GEMM 128x128x16, cp.async 2-stage --------
// C[M,N] = A[M,K] * B[K,N] (row-major) + epilogue
// A must be tf32-rounded fp32 (producers guarantee this) -> raw fragment loads.
// CVTB=1: B needs in-loop cvt (harness weights). CVTB=0: B pre-rounded.
// EPI bit0: +bias[col]   bit1: gelu (output tf32-rounded)   bit2: +res
template <int EPI, int CVTB>
__global__ __launch_bounds__(256, 2) void tgemm_kernel(
    const float* __restrict__ A, const float* __restrict__ Bm,
    float* __restrict__ C, const float* __restrict__ bias,
    const float* __restrict__ res, int M, int N, int K)
{
    __shared__ float As[2][128][20];
    __shared__ float Bs[2][16][136];
    int tid = threadIdx.x;
    int lane = tid & 31, warp = tid >> 5;
    int g = lane >> 2, tg = lane & 3;
    int mw = (warp & 3) << 5;
    int nw = (warp >> 2) << 6;
    int bm = blockIdx.y, bn = blockIdx.x;
    const float* Ab = A  + (size_t)bm * 128 * K;
    const float* Bb = Bm + (size_t)bn * 128;

    float acc[2][8][4];
    #pragma unroll
    for (int mi = 0; mi < 2; mi++)
        #pragma unroll
        for (int j = 0; j < 8; j++)
            #pragma unroll
            for (int q = 0; q < 4; q++) acc[mi][j][q] = 0.f;

    int am  = tid >> 1;
    int ak  = (tid & 1) << 3;
    int bkr = tid >> 5;
    int bn4 = lane << 2;

    cp_async16(&As[0][am][ak],       Ab + (size_t)am * K + ak);
    cp_async16(&As[0][am][ak + 4],   Ab + (size_t)am * K + ak + 4);
    cp_async16(&Bs[0][bkr][bn4],     Bb + (size_t)bkr * N + bn4);
    cp_async16(&Bs[0][bkr + 8][bn4], Bb + (size_t)(bkr + 8) * N + bn4);
    CP_COMMIT();

    int nk = K >> 4;
    for (int it = 0; it < nk; it++) {
        int buf = it & 1;
        CP_WAIT0();
        __syncthreads();
        if (it + 1 < nk) {
            int kt = (it + 1) << 4;
            int nb2 = buf ^ 1;
            cp_async16(&As[nb2][am][ak],       Ab + (size_t)am * K + kt + ak);
            cp_async16(&As[nb2][am][ak + 4],   Ab + (size_t)am * K + kt + ak + 4);
            cp_async16(&Bs[nb2][bkr][bn4],     Bb + (size_t)(kt + bkr) * N + bn4);
            cp_async16(&Bs[nb2][bkr + 8][bn4], Bb + (size_t)(kt + bkr + 8) * N + bn4);
            CP_COMMIT();
        }
        #pragma unroll
        for (int kk = 0; kk < 16; kk += 8) {
            uint32_t af[2][4], bf[8][2];
            #pragma unroll
            for (int mi = 0; mi < 2; mi++) {
                int r = mw + (mi << 4) + g;
                af[mi][0] = __float_as_uint(As[buf][r    ][kk + tg]);
                af[mi][1] = __float_as_uint(As[buf][r + 8][kk + tg]);
                af[mi][2] = __float_as_uint(As[buf][r    ][kk + tg + 4]);
                af[mi][3] = __float_as_uint(As[buf][r + 8][kk + tg + 4]);
            }
            #pragma unroll
            for (int j = 0; j < 8; j++) {
                if (CVTB) {
                    bf[j][0] = f2tf(Bs[buf][kk + tg    ][nw + (j << 3) + g]);
                    bf[j][1] = f2tf(Bs[buf][kk + tg + 4][nw + (j << 3) + g]);
                } else {
                    bf[j][0] = __float_as_uint(Bs[buf][kk + tg    ][nw + (j << 3) + g]);
                    bf[j][1] = __float_as_uint(Bs[buf][kk + tg + 4][nw + (j << 3) + g]);
                }
            }
            #pragma unroll
            for (int mi = 0; mi < 2; mi++)
                #pragma unroll
                for (int j = 0; j < 8; j++)
                    mma_tf32(acc[mi][j], af[mi], bf[j]);
        }
    }

    #pragma unroll
    for (int mi = 0; mi < 2; mi++) {
        int r0 = bm * 128 + mw + (mi << 4) + g;
        int r1 = r0 + 8;
        #pragma unroll
        for (int j = 0; j < 8; j++) {
            int c = bn * 128 + nw + (j << 3) + (tg << 1);
            float v0 = acc[mi][j][0], v1 = acc[mi][j][1];
            float v2 = acc[mi][j][2], v3 = acc[mi][j][3];
            if (EPI & 1) {
                float2 bv = *(const float2*)(bias + c);
                v0 += bv.x; v1 += bv.y; v2 += bv.x; v3 += bv.y;
            }
            if (EPI & 2) {   // gelu, output tf32-rounded (becomes GEMM-A input)
                v0 = rtf(geluf(v0)); v1 = rtf(geluf(v1));
                v2 = rtf(geluf(v2)); v3 = rtf(geluf(v3));
            }
            if (EPI & 4) {
                float2 ra = *(const float2*)(res + (size_t)r0 * N + c);
                float2 rb = *(const float2*)(res + (size_t)r1 * N + c);
                v0 += ra.x; v1 += ra.y; v2 += rb.x; v3 += rb.y;
            }
            float2 w0 = { v0, v1 }, w1 = { v2, v3 };
            *(float2*)(C + (size_t)r0 * N + c) = w0;
            *(float2*)(C + (size_t)r1 * N + c) = w1;
        }
    }
}

// ---------------- flash attention, tf32 tensor cores ------------------------
// Block: (bh, 64 q-rows). 8 warps as 4(m)x2(n). Warp tile 16x32.
// V kept row-major [s][e] pitch 72 (no transpose): PV B-fragments read
// Vs[(kk+tg)*72 + n], banks (8*tg+g) all-distinct -> conflict-free.
#define QP 68
#define VP 72
#define FLASH_SMEM_FLOATS (3*64*QP + 64*VP + 2*64*2)
#define FLASH_SMEM_BYTES (FLASH_SMEM_FLOATS * 4)

__global__ __launch_bounds__(256, 2) void flash_attn_kernel()
{
    extern __shared__ uint32_t usm[];
    uint32_t* Qs = usm;                 // [64][QP]
    uint32_t* Ks = Qs + 64 * QP;        // [64][QP]
    uint32_t* Ps = Ks + 64 * QP;        // [64][QP]
    uint32_t* Vs = Ps + 64 * QP;        // [64][VP]
    float* redm  = (float*)(Vs + 64 * VP);
    float* reds  = redm + 64 * 2;

    int bh = blockIdx.y;
    int b = bh >> 4, h = bh & 15;
    int t0 = blockIdx.x * 64;
    int tid = threadIdx.x;
    int lane = tid & 31, warp = tid >> 5;
    int g = lane >> 2, tg = lane & 3;
    int wm = warp & 3, wn = warp >> 2;
    int m0r = (wm << 4) + g;
    int nb  = wn << 5;

    const float* qbase = g_qkv + ((size_t)b * T_) * TD3_ + h * 64;

    #pragma unroll
    for (int i = 0; i < 4; i++) {
        int fid = tid + i * 256;
        int row = fid >> 4;
        int e4  = (fid & 15) << 2;
        float4 q4 = *(const float4*)(qbase + (size_t)(t0 + row) * TD3_ + e4);
        uint4 u = { f2tf(q4.x), f2tf(q4.y), f2tf(q4.z), f2tf(q4.w) };
        *(uint4*)&Qs[row * QP + e4] = u;
    }

    float accO[4][4];
    #pragma unroll
    for (int j = 0; j < 4; j++)
        #pragma unroll
        for (int q = 0; q < 4; q++) accO[j][q] = 0.f;
    float m0 = -3.0e38f, m1 = -3.0e38f, l0 = 0.f, l1 = 0.f;

    for (int st = 0; st < 16; st++) {
        int s0_ = st * 64;
        __syncthreads();
        #pragma unroll
        for (int i = 0; i < 4; i++) {
            int fid = tid + i * 256;
            int row = fid >> 4;
            int e4  = (fid & 15) << 2;
            float4 k4 = *(const float4*)(qbase + 1024 + (size_t)(s0_ + row) * TD3_ + e4);
            uint4 uk = { f2tf(k4.x), f2tf(k4.y), f2tf(k4.z), f2tf(k4.w) };
            *(uint4*)&Ks[row * QP + e4] = uk;
            float4 v4 = *(const float4*)(qbase + 2048 + (size_t)(s0_ + row) * TD3_ + e4);
            uint4 uv = { f2tf(v4.x), f2tf(v4.y), f2tf(v4.z), f2tf(v4.w) };
            *(uint4*)&Vs[row * VP + e4] = uv;
        }
        __syncthreads();

        // S = Q K^T
        float sacc[4][4];
        #pragma unroll
        for (int j = 0; j < 4; j++)
            #pragma unroll
            for (int q = 0; q < 4; q++) sacc[j][q] = 0.f;
        #pragma unroll
        for (int kk = 0; kk < 64; kk += 8) {
            uint32_t af[4], bf[4][2];
            af[0] = Qs[m0r * QP + kk + tg];
            af[1] = Qs[(m0r + 8) * QP + kk + tg];
            af[2] = Qs[m0r * QP + kk + tg + 4];
            af[3] = Qs[(m0r + 8) * QP + kk + tg + 4];
            #pragma unroll
            for (int j = 0; j < 4; j++) {
                int n = nb + (j << 3) + g;
                bf[j][0] = Ks[n * QP + kk + tg];
                bf[j][1] = Ks[n * QP + kk + tg + 4];
            }
            #pragma unroll
            for (int j = 0; j < 4; j++) mma_tf32(sacc[j], af, bf[j]);
        }

        float rmax0 = -3.0e38f, rmax1 = -3.0e38f;
        #pragma unroll
        for (int j = 0; j < 4; j++) {
            #pragma unroll
            for (int q = 0; q < 4; q++) sacc[j][q] *= 0.125f;
            rmax0 = fmaxf(rmax0, fmaxf(sacc[j][0], sacc[j][1]));
            rmax1 = fmaxf(rmax1, fmaxf(sacc[j][2], sacc[j][3]));
        }
        rmax0 = fmaxf(rmax0, __shfl_xor_sync(0xffffffffu, rmax0, 1));
        rmax0 = fmaxf(rmax0, __shfl_xor_sync(0xffffffffu, rmax0, 2));
        rmax1 = fmaxf(rmax1, __shfl_xor_sync(0xffffffffu, rmax1, 1));
        rmax1 = fmaxf(rmax1, __shfl_xor_sync(0xffffffffu, rmax1, 2));
        if (tg == 0) {
            redm[m0r * 2 + wn]       = rmax0;
            redm[(m0r + 8) * 2 + wn] = rmax1;
        }
        __syncthreads();
        float mn0 = fmaxf(m0, fmaxf(redm[m0r * 2], redm[m0r * 2 + 1]));
        float mn1 = fmaxf(m1, fmaxf(redm[(m0r + 8) * 2], redm[(m0r + 8) * 2 + 1]));
        float alpha0 = __expf(m0 - mn0);
        float alpha1 = __expf(m1 - mn1);
        m0 = mn0; m1 = mn1;

        float rs0 = 0.f, rs1 = 0.f;
        #pragma unroll
        for (int j = 0; j < 4; j++) {
            float p00 = __expf(sacc[j][0] - mn0);
            float p01 = __expf(sacc[j][1] - mn0);
            float p10 = __expf(sacc[j][2] - mn1);
            float p11 = __expf(sacc[j][3] - mn1);
            rs0 += p00 + p01; rs1 += p10 + p11;
            int col = nb + (j << 3) + (tg << 1);
            uint2 u0 = { f2tf(p00), f2tf(p01) };
            uint2 u1 = { f2tf(p10), f2tf(p11) };
            *(uint2*)&Ps[m0r * QP + col]       = u0;
            *(uint2*)&Ps[(m0r + 8) * QP + col] = u1;
        }
        rs0 += __shfl_xor_sync(0xffffffffu, rs0, 1);
        rs0 += __shfl_xor_sync(0xffffffffu, rs0, 2);
        rs1 += __shfl_xor_sync(0xffffffffu, rs1, 1);
        rs1 += __shfl_xor_sync(0xffffffffu, rs1, 2);
        if (tg == 0) {
            reds[m0r * 2 + wn]       = rs0;
            reds[(m0r + 8) * 2 + wn] = rs1;
        }
        #pragma unroll
        for (int j = 0; j < 4; j++) {
            accO[j][0] *= alpha0; accO[j][1] *= alpha0;
            accO[j][2] *= alpha1; accO[j][3] *= alpha1;
        }
        __syncthreads();
        l0 = l0 * alpha0 + reds[m0r * 2] + reds[m0r * 2 + 1];
        l1 = l1 * alpha1 + reds[(m0r + 8) * 2] + reds[(m0r + 8) * 2 + 1];

        // O += P @ V  (V row-major: B[k=s][n=e] = Vs[(kk+tg)*VP + n])
        #pragma unroll
        for (int kk = 0; kk < 64; kk += 8) {
            uint32_t af[4], bf[4][2];
            af[0] = Ps[m0r * QP + kk + tg];
            af[1] = Ps[(m0r + 8) * QP + kk + tg];
            af[2] = Ps[m0r * QP + kk + tg + 4];
            af[3] = Ps[(m0r + 8) * QP + kk + tg + 4];
            #pragma unroll
            for (int j = 0; j < 4; j++) {
                int n = nb + (j << 3) + g;
                bf[j][0] = Vs[(kk + tg) * VP + n];
                bf[j][1] = Vs[(kk + tg + 4) * VP + n];
            }
            #pragma unroll
            for (int j = 0; j < 4; j++) mma_tf32(accO[j], af, bf[j]);
        }
    }

    float inv0 = 1.0f / l0;
    float inv1 = 1.0f / l1;
    float* out0 = g_ctx + ((size_t)b * T_ + t0 + m0r) * D_ + h * 64;
    float* out1 = out0 + (size_t)8 * D_;
    #pragma unroll
    for (int j = 0; j < 4; j++) {
        int col = nb + (j << 3) + (tg << 1);
        float2 w0 = { rtf(accO[j][0] * inv0), rtf(accO[j][1] * inv0) };
        float2 w1 = { rtf(accO[j][2] * inv1), rtf(accO[j][3] * inv1) };
        *(float2*)(out0 + col) = w0;
        *(float2*)(out1 + col) = w1;
    }
}

// ---------------- launcher --------------------------------------------------
extern "C" void kernel_launch(void* const* d_in, const int* in_sizes, int n_in,
                              void* d_out, int out_size)
{
    const float* x    = (const float*)d_in[0];
    const float* ln1g = (const float*)d_in[1];
    const float* ln1b = (const float*)d_in[2];
    const float* ln2g = (const float*)d_in[3];
    const float* ln2b = (const float*)d_in[4];
    const float* Wq   = (const float*)d_in[5];
    const float* bq   = (const float*)d_in[6];
    const float* Wk   = (const float*)d_in[7];
    const float* bk   = (const float*)d_in[8];
    const float* Wv   = (const float*)d_in[9];
    const float* bv   = (const float*)d_in[10];
    const float* Wo   = (const float*)d_in[11];
    const float* bo   = (const float*)d_in[12];
    const float* W1   = (const float*)d_in[13];
    const float* b1   = (const float*)d_in[14];
    const float* W2   = (const float*)d_in[15];
    const float* b2   = (const float*)d_in[16];
    float* out = (float*)d_out;

    static float* h_    = nullptr;
    static float* qkv_  = nullptr;
    static float* wcat_ = nullptr;
    static float* bcat_ = nullptr;
    static float* ctx_  = nullptr;
    static float* ffa_  = nullptr;
    if (!h_) {   // pointer cache only — identical work every call
        cudaGetSymbolAddress((void**)&h_,    g_h);
        cudaGetSymbolAddress((void**)&qkv_,  g_qkv);
        cudaGetSymbolAddress((void**)&wcat_, g_wcat);
        cudaGetSymbolAddress((void**)&bcat_, g_bcat);
        cudaGetSymbolAddress((void**)&ctx_,  g_ctx);
        cudaGetSymbolAddress((void**)&ffa_,  g_ffa);
        cudaFuncSetAttribute(flash_attn_kernel,
                             cudaFuncAttributeMaxDynamicSharedMemorySize,
                             FLASH_SMEM_BYTES);
    }

    // 1) repack QKV weights (tf32-rounded)
    repack_kernel<<<(D_ * TD3_ + 255) / 256, 256>>>(Wq, Wk, Wv, bq, bk, bv);
    // 2) ln1 (tf32-rounded output)
    ln_kernel<<<BT_, 256>>>(x, ln1g, ln1b, h_);
    // 3) QKV = h @ Wcat + bcat   (both operands pre-rounded -> CVTB=0)
    tgemm_kernel<1, 0><<<dim3(TD3_ / 128, BT_ / 128), 256>>>(h_, wcat_, qkv_, bcat_, nullptr,
                                                             BT_, TD3_, D_);
    // 4-6) fused attention -> g_ctx (tf32-rounded)
    flash_attn_kernel<<<dim3(16, B_ * H_), 256, FLASH_SMEM_BYTES>>>();
    // 7) X1 = x + ctx @ Wo + bo
    tgemm_kernel<5, 1><<<dim3(D_ / 128, BT_ / 128), 256>>>(ctx_, Wo, out, bo, x,
                                                           BT_, D_, D_);
    // 8) ln2 (tf32-rounded output)
    ln_kernel<<<BT_, 256>>>(out, ln2g, ln2b, h_);
    // 9) ffa = gelu(h @ W1 + b1)  (tf32-rounded output)
    tgemm_kernel<3, 1><<<dim3(FF_ / 128, BT_ / 128), 256>>>(h_, W1, ffa_, b1, nullptr,
                                                            BT_, FF_, D_);
    // 10) out = X1 + ffa @ W2 + b2
    tgemm_kernel<5, 1><<<dim3(D_ / 128, BT_ / 128), 256>>>(ffa_, W2, out, b2, out,
                                                           BT_, D_, FF_);
}

// round 8
// speedup vs baseline: 2.7724x; 1.0179x over previous
#include <cuda_runtime.h>
#include <cstdint>
#include <cstddef>

#define B_  8
#define T_  1024
#define D_  1024
#define H_  16
#define HD_ 64
#define FF_ 4096
#define BT_ (B_*T_)            // 8192
#define TD3_ (3*D_)            // 3072

// ---------------- scratch (device globals: allocation-guard-safe) ----------
__device__ float g_h[(size_t)BT_ * D_];          // 32 MB  (tf32-rounded)
__device__ float g_qkv[(size_t)BT_ * TD3_];      // 96 MB  (tf32-rounded)
__device__ float g_wcat[(size_t)D_ * TD3_];      // 12 MB  (tf32-rounded)
__device__ float g_bcat[TD3_];
__device__ float g_ctx[(size_t)BT_ * D_];        // 32 MB  (tf32-rounded)
__device__ float g_ffa[(size_t)BT_ * FF_];       // 128 MB (tf32-rounded)
__device__ float g_wrnd[(size_t)D_*D_ + (size_t)D_*FF_ + (size_t)FF_*D_]; // 36 MB

// ---------------- helpers ---------------------------------------------------
__device__ __forceinline__ float geluf(float x) {
    return 0.5f * x * (1.0f + erff(x * 0.70710678118654752f));
}
__device__ __forceinline__ uint32_t f2tf(float x) {
    uint32_t r; asm("cvt.rna.tf32.f32 %0, %1;" : "=r"(r) : "f"(x)); return r;
}
__device__ __forceinline__ float rtf(float x) {   // tf32-rounded fp32 value
    return __uint_as_float(f2tf(x));
}
__device__ __forceinline__ void mma_tf32(float c[4], const uint32_t a[4], const uint32_t b[2]) {
    asm volatile(
        "mma.sync.aligned.m16n8k8.row.col.f32.tf32.tf32.f32 "
        "{%0,%1,%2,%3}, {%4,%5,%6,%7}, {%8,%9}, {%0,%1,%2,%3};"
        : "+f"(c[0]), "+f"(c[1]), "+f"(c[2]), "+f"(c[3])
        : "r"(a[0]), "r"(a[1]), "r"(a[2]), "r"(a[3]), "r"(b[0]), "r"(b[1]));
}
__device__ __forceinline__ void cp_async16(void* sptr, const void* gptr) {
    uint32_t s = (uint32_t)__cvta_generic_to_shared(sptr);
    asm volatile("cp.async.cg.shared.global [%0], [%1], 16;" :: "r"(s), "l"(gptr));
}
#define CP_COMMIT() asm volatile("cp.async.commit_group;")
#define CP_WAIT0()  asm volatile("cp.async.wait_group 0;")

// ---------------- weight repack: Wq/Wk/Wv [H,D,HD] -> Wcat [D, 3D] ----------
__global__ __launch_bounds__(256) void repack_kernel(
    const float* __restrict__ Wq, const float* __restrict__ Wk, const float* __restrict__ Wv,
    const float* __restrict__ bq, const float* __restrict__ bk, const float* __restrict__ bv)
{
    int t = blockIdx.x * blockDim.x + threadIdx.x;
    if (t >= D_ * TD3_) return;
    int d = t / TD3_;
    int n = t - d * TD3_;
    int part = n >> 10;
    int m = n & (D_ - 1);
    int h = m >> 6, e = m & 63;
    const float* W = (part == 0) ? Wq : (part == 1) ? Wk : Wv;
    g_wcat[t] = rtf(W[((size_t)h * D_ + d) * HD_ + e]);
    if (d == 0) {
        const float* bb = (part == 0) ? bq : (part == 1) ? bk : bv;
        g_bcat[n] = bb[m];
    }
}

// ---------------- round Wo|W1|W2 into g_wrnd (float4) -----------------------
#define WRND_TOTAL4 ((D_*D_ + D_*FF_ + FF_*D_) / 4)
__global__ __launch_bounds__(256) void wround_kernel(
    const float* __restrict__ Wo, const float* __restrict__ W1,
    const float* __restrict__ W2)
{
    int t = blockIdx.x * blockDim.x + threadIdx.x;
    if (t >= WRND_TOTAL4) return;
    int i4 = t << 2;
    const float* src;
    if (i4 < D_ * D_)                 src = Wo + i4;
    else if (i4 < D_ * D_ + D_ * FF_) src = W1 + (i4 - D_ * D_);
    else                              src = W2 + (i4 - D_ * D_ - D_ * FF_);
    float4 v = *(const float4*)src;
    float4 o = { rtf(v.x), rtf(v.y), rtf(v.z), rtf(v.w) };
    *(float4*)(g_wrnd + i4) = o;
}

// ---------------- layernorm (output tf32-rounded) ---------------------------
__global__ __launch_bounds__(256) void ln_kernel(
    const float* __restrict__ x, const float* __restrict__ g,
    const float* __restrict__ bta, float* __restrict__ y)
{
    int row = blockIdx.x;
    int tid = threadIdx.x;
    const float4* xr = (const float4*)(x + (size_t)row * D_);
    float4 v = xr[tid];
    float s  = v.x + v.y + v.z + v.w;
    float ss = v.x*v.x + v.y*v.y + v.z*v.z + v.w*v.w;
    __shared__ float sh_s[8], sh_ss[8];
    #pragma unroll
    for (int o = 16; o > 0; o >>= 1) {
        s  += __shfl_down_sync(0xffffffffu, s,  o);
        ss += __shfl_down_sync(0xffffffffu, ss, o);
    }
    if ((tid & 31) == 0) { sh_s[tid >> 5] = s; sh_ss[tid >> 5] = ss; }
    __syncthreads();
    float S = 0.f, SS = 0.f;
    #pragma unroll
    for (int i = 0; i < 8; i++) { S += sh_s[i]; SS += sh_ss[i]; }
    float mu  = S * (1.0f / D_);
    float var = SS * (1.0f / D_) - mu * mu;
    float inv = rsqrtf(var + 1e-5f);
    float4 g4 = ((const float4*)g)[tid];
    float4 b4 = ((const float4*)bta)[tid];
    float4 o;
    o.x = rtf((v.x - mu) * inv * g4.x + b4.x);
    o.y = rtf((v.y - mu) * inv * g4.y + b4.y);
    o.z = rtf((v.z - mu) * inv * g4.z + b4.z);
    o.w = rtf((v.w - mu) * inv * g4.w + b4.w);
    ((float4*)(y + (size_t)row * D_))[tid] = o;
}

// ---------------- tf32 tensor-core GEMM 128x128x16, cp.async 2-stage --------
// C[M,N] = A[M,K] * B[K,N] (row-major) + epilogue. A and B pre-rounded tf32.
// EPI bit0: +bias  bit1: gelu (rounds)  bit2: +res  bit3: round output
template <int EPI>
__global__ __launch_bounds__(256, 2) void tgemm_kernel(
    const float* __restrict__ A, const float* __restrict__ Bm,
    float* __restrict__ C, const float* __restrict__ bias,
    const float* __restrict__ res, int M, int N, int K)
{
    __shared__ float As[2][128][20];
    __shared__ float Bs[2][16][136];
    int tid = threadIdx.x;
    int lane = tid & 31, warp = tid >> 5;
    int g = lane >> 2, tg = lane & 3;
    int mw = (warp & 3) << 5;
    int nw = (warp >> 2) << 6;
    int bm = blockIdx.y, bn = blockIdx.x;
    const float* Ab = A  + (size_t)bm * 128 * K;
    const float* Bb = Bm + (size_t)bn * 128;

    float acc[2][8][4];
    #pragma unroll
    for (int mi = 0; mi < 2; mi++)
        #pragma unroll
        for (int j = 0; j < 8; j++)
            #pragma unroll
            for (int q = 0; q < 4; q++) acc[mi][j][q] = 0.f;

    int am  = tid >> 1;
    int ak  = (tid & 1) << 3;
    int bkr = tid >> 5;
    int bn4 = lane << 2;

    cp_async16(&As[0][am][ak],       Ab + (size_t)am * K + ak);
    cp_async16(&As[0][am][ak + 4],   Ab + (size_t)am * K + ak + 4);
    cp_async16(&Bs[0][bkr][bn4],     Bb + (size_t)bkr * N + bn4);
    cp_async16(&Bs[0][bkr + 8][bn4], Bb + (size_t)(bkr + 8) * N + bn4);
    CP_COMMIT();

    int nk = K >> 4;
    for (int it = 0; it < nk; it++) {
        int buf = it & 1;
        CP_WAIT0();
        __syncthreads();
        if (it + 1 < nk) {
            int kt = (it + 1) << 4;
            int nb2 = buf ^ 1;
            cp_async16(&As[nb2][am][ak],       Ab + (size_t)am * K + kt + ak);
            cp_async16(&As[nb2][am][ak + 4],   Ab + (size_t)am * K + kt + ak + 4);
            cp_async16(&Bs[nb2][bkr][bn4],     Bb + (size_t)(kt + bkr) * N + bn4);
            cp_async16(&Bs[nb2][bkr + 8][bn4], Bb + (size_t)(kt + bkr + 8) * N + bn4);
            CP_COMMIT();
        }
        #pragma unroll
        for (int kk = 0; kk < 16; kk += 8) {
            uint32_t af[2][4], bf[8][2];
            #pragma unroll
            for (int mi = 0; mi < 2; mi++) {
                int r = mw + (mi << 4) + g;
                af[mi][0] = __float_as_uint(As[buf][r    ][kk + tg]);
                af[mi][1] = __float_as_uint(As[buf][r + 8][kk + tg]);
                af[mi][2] = __float_as_uint(As[buf][r    ][kk + tg + 4]);
                af[mi][3] = __float_as_uint(As[buf][r + 8][kk + tg + 4]);
            }
            #pragma unroll
            for (int j = 0; j < 8; j++) {
                bf[j][0] = __float_as_uint(Bs[buf][kk + tg    ][nw + (j << 3) + g]);
                bf[j][1] = __float_as_uint(Bs[buf][kk + tg + 4][nw + (j << 3) + g]);
            }
            #pragma unroll
            for (int mi = 0; mi < 2; mi++)
                #pragma unroll
                for (int j = 0; j < 8; j++)
                    mma_tf32(acc[mi][j], af[mi], bf[j]);
        }
    }

    #pragma unroll
    for (int mi = 0; mi < 2; mi++) {
        int r0 = bm * 128 + mw + (mi << 4) + g;
        int r1 = r0 + 8;
        #pragma unroll
        for (int j = 0; j < 8; j++) {
            int c = bn * 128 + nw + (j << 3) + (tg << 1);
            float v0 = acc[mi][j][0], v1 = acc[mi][j][1];
            float v2 = acc[mi][j][2], v3 = acc[mi][j][3];
            if (EPI & 1) {
                float2 bv = *(const float2*)(bias + c);
                v0 += bv.x; v1 += bv.y; v2 += bv.x; v3 += bv.y;
            }
            if (EPI & 2) {
                v0 = rtf(geluf(v0)); v1 = rtf(geluf(v1));
                v2 = rtf(geluf(v2)); v3 = rtf(geluf(v3));
            }
            if (EPI & 4) {
                float2 ra = *(const float2*)(res + (size_t)r0 * N + c);
                float2 rb = *(const float2*)(res + (size_t)r1 * N + c);
                v0 += ra.x; v1 += ra.y; v2 += rb.x; v3 += rb.y;
            }
            if (EPI & 8) {
                v0 = rtf(v0); v1 = rtf(v1); v2 = rtf(v2); v3 = rtf(v3);
            }
            float2 w0 = { v0, v1 }, w1 = { v2, v3 };
            *(float2*)(C + (size_t)r0 * N + c) = w0;
            *(float2*)(C + (size_t)r1 * N + c) = w1;
        }
    }
}

// ---------------- flash attention, tf32 tensor cores + cp.async K/V --------
// Block: (bh, 64 q-rows). 8 warps 4(m)x2(n), warp tile 16x32.
// qkv pre-rounded tf32 -> raw loads, no cvt. K/V double-buffered via cp.async.
#define QP 68
#define VP 72
#define FLASH_SMEM_FLOATS (64*QP + 2*64*QP + 2*64*VP + 64*QP + 256)
#define FLASH_SMEM_BYTES (FLASH_SMEM_FLOATS * 4)

__global__ __launch_bounds__(256, 2) void flash_attn_kernel()
{
    extern __shared__ uint32_t usm[];
    uint32_t* Qs = usm;                    // [64][QP]
    uint32_t* Ks = Qs + 64 * QP;           // [2][64][QP]
    uint32_t* Vs = Ks + 2 * 64 * QP;       // [2][64][VP]
    uint32_t* Ps = Vs + 2 * 64 * VP;       // [64][QP]
    float* redm  = (float*)(Ps + 64 * QP); // [128]
    float* reds  = redm + 128;             // [128]

    int bh = blockIdx.y;
    int b = bh >> 4, h = bh & 15;
    int t0 = blockIdx.x * 64;
    int tid = threadIdx.x;
    int lane = tid & 31, warp = tid >> 5;
    int g = lane >> 2, tg = lane & 3;
    int wm = warp & 3, wn = warp >> 2;
    int m0r = (wm << 4) + g;
    int nb  = wn << 5;

    const float* qbase = g_qkv + ((size_t)b * T_) * TD3_ + h * 64;
    int lrow = tid >> 4;              // 0..15 (+16 per iter)
    int le4  = (tid & 15) << 2;       // 0..60

    // prefetch Q (raw, already tf32)
    #pragma unroll
    for (int i = 0; i < 4; i++) {
        int row = lrow + i * 16;
        cp_async16(&Qs[row * QP + le4], qbase + (size_t)(t0 + row) * TD3_ + le4);
    }
    CP_COMMIT();
    // prefetch K/V tile 0
    #pragma unroll
    for (int i = 0; i < 4; i++) {
        int row = lrow + i * 16;
        cp_async16(&Ks[row * QP + le4], qbase + 1024 + (size_t)row * TD3_ + le4);
        cp_async16(&Vs[row * VP + le4], qbase + 2048 + (size_t)row * TD3_ + le4);
    }
    CP_COMMIT();

    float accO[4][4];
    #pragma unroll
    for (int j = 0; j < 4; j++)
        #pragma unroll
        for (int q = 0; q < 4; q++) accO[j][q] = 0.f;
    float m0 = -3.0e38f, m1 = -3.0e38f, l0 = 0.f, l1 = 0.f;

    for (int st = 0; st < 16; st++) {
        int buf = st & 1;
        uint32_t* Kb = Ks + buf * 64 * QP;
        uint32_t* Vb = Vs + buf * 64 * VP;
        CP_WAIT0();
        __syncthreads();
        if (st + 1 < 16) {
            int s1 = (st + 1) * 64;
            uint32_t* Kn = Ks + (buf ^ 1) * 64 * QP;
            uint32_t* Vn = Vs + (buf ^ 1) * 64 * VP;
            #pragma unroll
            for (int i = 0; i < 4; i++) {
                int row = lrow + i * 16;
                cp_async16(&Kn[row * QP + le4], qbase + 1024 + (size_t)(s1 + row) * TD3_ + le4);
                cp_async16(&Vn[row * VP + le4], qbase + 2048 + (size_t)(s1 + row) * TD3_ + le4);
            }
            CP_COMMIT();
        }

        // S = Q K^T
        float sacc[4][4];
        #pragma unroll
        for (int j = 0; j < 4; j++)
            #pragma unroll
            for (int q = 0; q < 4; q++) sacc[j][q] = 0.f;
        #pragma unroll
        for (int kk = 0; kk < 64; kk += 8) {
            uint32_t af[4], bf[4][2];
            af[0] = Qs[m0r * QP + kk + tg];
            af[1] = Qs[(m0r + 8) * QP + kk + tg];
            af[2] = Qs[m0r * QP + kk + tg + 4];
            af[3] = Qs[(m0r + 8) * QP + kk + tg + 4];
            #pragma unroll
            for (int j = 0; j < 4; j++) {
                int n = nb + (j << 3) + g;
                bf[j][0] = Kb[n * QP + kk + tg];
                bf[j][1] = Kb[n * QP + kk + tg + 4];
            }
            #pragma unroll
            for (int j = 0; j < 4; j++) mma_tf32(sacc[j], af, bf[j]);
        }

        float rmax0 = -3.0e38f, rmax1 = -3.0e38f;
        #pragma unroll
        for (int j = 0; j < 4; j++) {
            #pragma unroll
            for (int q = 0; q < 4; q++) sacc[j][q] *= 0.125f;
            rmax0 = fmaxf(rmax0, fmaxf(sacc[j][0], sacc[j][1]));
            rmax1 = fmaxf(rmax1, fmaxf(sacc[j][2], sacc[j][3]));
        }
        rmax0 = fmaxf(rmax0, __shfl_xor_sync(0xffffffffu, rmax0, 1));
        rmax0 = fmaxf(rmax0, __shfl_xor_sync(0xffffffffu, rmax0, 2));
        rmax1 = fmaxf(rmax1, __shfl_xor_sync(0xffffffffu, rmax1, 1));
        rmax1 = fmaxf(rmax1, __shfl_xor_sync(0xffffffffu, rmax1, 2));
        if (tg == 0) {
            redm[m0r * 2 + wn]       = rmax0;
            redm[(m0r + 8) * 2 + wn] = rmax1;
        }
        __syncthreads();
        float mn0 = fmaxf(m0, fmaxf(redm[m0r * 2], redm[m0r * 2 + 1]));
        float mn1 = fmaxf(m1, fmaxf(redm[(m0r + 8) * 2], redm[(m0r + 8) * 2 + 1]));
        float alpha0 = __expf(m0 - mn0);
        float alpha1 = __expf(m1 - mn1);
        m0 = mn0; m1 = mn1;

        float rs0 = 0.f, rs1 = 0.f;
        #pragma unroll
        for (int j = 0; j < 4; j++) {
            float p00 = __expf(sacc[j][0] - mn0);
            float p01 = __expf(sacc[j][1] - mn0);
            float p10 = __expf(sacc[j][2] - mn1);
            float p11 = __expf(sacc[j][3] - mn1);
            rs0 += p00 + p01; rs1 += p10 + p11;
            int col = nb + (j << 3) + (tg << 1);
            uint2 u0 = { f2tf(p00), f2tf(p01) };
            uint2 u1 = { f2tf(p10), f2tf(p11) };
            *(uint2*)&Ps[m0r * QP + col]       = u0;
            *(uint2*)&Ps[(m0r + 8) * QP + col] = u1;
        }
        rs0 += __shfl_xor_sync(0xffffffffu, rs0, 1);
        rs0 += __shfl_xor_sync(0xffffffffu, rs0, 2);
        rs1 += __shfl_xor_sync(0xffffffffu, rs1, 1);
        rs1 += __shfl_xor_sync(0xffffffffu, rs1, 2);
        if (tg == 0) {
            reds[m0r * 2 + wn]       = rs0;
            reds[(m0r + 8) * 2 + wn] = rs1;
        }
        #pragma unroll
        for (int j = 0; j < 4; j++) {
            accO[j][0] *= alpha0; accO[j][1] *= alpha0;
            accO[j][2] *= alpha1; accO[j][3] *= alpha1;
        }
        __syncthreads();
        l0 = l0 * alpha0 + reds[m0r * 2] + reds[m0r * 2 + 1];
        l1 = l1 * alpha1 + reds[(m0r + 8) * 2] + reds[(m0r + 8) * 2 + 1];

        // O += P @ V
        #pragma unroll
        for (int kk = 0; kk < 64; kk += 8) {
            uint32_t af[4], bf[4][2];
            af[0] = Ps[m0r * QP + kk + tg];
            af[1] = Ps[(m0r + 8) * QP + kk + tg];
            af[2] = Ps[m0r * QP + kk + tg + 4];
            af[3] = Ps[(m0r + 8) * QP + kk + tg + 4];
            #pragma unroll
            for (int j = 0; j < 4; j++) {
                int n = nb + (j << 3) + g;
                bf[j][0] = Vb[(kk + tg) * VP + n];
                bf[j][1] = Vb[(kk + tg + 4) * VP + n];
            }
            #pragma unroll
            for (int j = 0; j < 4; j++) mma_tf32(accO[j], af, bf[j]);
        }
    }

    float inv0 = 1.0f / l0;
    float inv1 = 1.0f / l1;
    float* out0 = g_ctx + ((size_t)b * T_ + t0 + m0r) * D_ + h * 64;
    float* out1 = out0 + (size_t)8 * D_;
    #pragma unroll
    for (int j = 0; j < 4; j++) {
        int col = nb + (j << 3) + (tg << 1);
        float2 w0 = { rtf(accO[j][0] * inv0), rtf(accO[j][1] * inv0) };
        float2 w1 = { rtf(accO[j][2] * inv1), rtf(accO[j][3] * inv1) };
        *(float2*)(out0 + col) = w0;
        *(float2*)(out1 + col) = w1;
    }
}

// ---------------- launcher --------------------------------------------------
extern "C" void kernel_launch(void* const* d_in, const int* in_sizes, int n_in,
                              void* d_out, int out_size)
{
    const float* x    = (const float*)d_in[0];
    const float* ln1g = (const float*)d_in[1];
    const float* ln1b = (const float*)d_in[2];
    const float* ln2g = (const float*)d_in[3];
    const float* ln2b = (const float*)d_in[4];
    const float* Wq   = (const float*)d_in[5];
    const float* bq   = (const float*)d_in[6];
    const float* Wk   = (const float*)d_in[7];
    const float* bk   = (const float*)d_in[8];
    const float* Wv   = (const float*)d_in[9];
    const float* bv   = (const float*)d_in[10];
    const float* Wo   = (const float*)d_in[11];
    const float* bo   = (const float*)d_in[12];
    const float* W1   = (const float*)d_in[13];
    const float* b1   = (const float*)d_in[14];
    const float* W2   = (const float*)d_in[15];
    const float* b2   = (const float*)d_in[16];
    float* out = (float*)d_out;

    static float* h_    = nullptr;
    static float* qkv_  = nullptr;
    static float* wcat_ = nullptr;
    static float* bcat_ = nullptr;
    static float* ctx_  = nullptr;
    static float* ffa_  = nullptr;
    static float* wrnd_ = nullptr;
    if (!h_) {   // pointer cache only — identical work every call
        cudaGetSymbolAddress((void**)&h_,    g_h);
        cudaGetSymbolAddress((void**)&qkv_,  g_qkv);
        cudaGetSymbolAddress((void**)&wcat_, g_wcat);
        cudaGetSymbolAddress((void**)&bcat_, g_bcat);
        cudaGetSymbolAddress((void**)&ctx_,  g_ctx);
        cudaGetSymbolAddress((void**)&ffa_,  g_ffa);
        cudaGetSymbolAddress((void**)&wrnd_, g_wrnd);
        cudaFuncSetAttribute(flash_attn_kernel,
                             cudaFuncAttributeMaxDynamicSharedMemorySize,
                             FLASH_SMEM_BYTES);
    }
    float* wo_r = wrnd_;
    float* w1_r = wrnd_ + (size_t)D_ * D_;
    float* w2_r = wrnd_ + (size_t)D_ * D_ + (size_t)D_ * FF_;

    // 1) weight prep (rounded)
    repack_kernel<<<(D_ * TD3_ + 255) / 256, 256>>>(Wq, Wk, Wv, bq, bk, bv);
    wround_kernel<<<(WRND_TOTAL4 + 255) / 256, 256>>>(Wo, W1, W2);
    // 2) ln1
    ln_kernel<<<BT_, 256>>>(x, ln1g, ln1b, h_);
    // 3) QKV = h @ Wcat + bcat (rounded output for flash)
    tgemm_kernel<9><<<dim3(TD3_ / 128, BT_ / 128), 256>>>(h_, wcat_, qkv_, bcat_, nullptr,
                                                          BT_, TD3_, D_);
    // 4-6) fused attention -> g_ctx (rounded)
    flash_attn_kernel<<<dim3(16, B_ * H_), 256, FLASH_SMEM_BYTES>>>();
    // 7) X1 = x + ctx @ Wo + bo
    tgemm_kernel<5><<<dim3(D_ / 128, BT_ / 128), 256>>>(ctx_, wo_r, out, bo, x,
                                                        BT_, D_, D_);
    // 8) ln2
    ln_kernel<<<BT_, 256>>>(out, ln2g, ln2b, h_);
    // 9) ffa = gelu(h @ W1 + b1) (rounded via gelu path)
    tgemm_kernel<3><<<dim3(FF_ / 128, BT_ / 128), 256>>>(h_, w1_r, ffa_, b1, nullptr,
                                                         BT_, FF_, D_);
    // 10) out = X1 + ffa @ W2 + b2
    tgemm_kernel<5><<<dim3(D_ / 128, BT_ / 128), 256>>>(ffa_, w2_r, out, b2, out,
                                                        BT_, D_, FF_);
}